// round 9
// baseline (speedup 1.0000x reference)
#include <cuda_runtime.h>
#include <math.h>
#include <stdint.h>

#define BB    256
#define KTOT  768        // 3 taps * 256 conv-out channels

// ---------------------------------------------------------------------------
// Static device scratch
// ---------------------------------------------------------------------------
__device__ __align__(128) float    g_VmaxT [512 * 128];     // enemy pairwise-max emb [c][p]
__device__ __align__(128) float    g_VmaxTf[512 * 128];     // friend
__device__ __align__(128) uint32_t g_U2Thi [KTOT * 128];    // enemy U tf32 hi
__device__ __align__(128) uint32_t g_U2Tlo [KTOT * 128];    // enemy U tf32 lo
__device__ __align__(128) uint32_t g_U2Tfhi[KTOT * 128];    // friend U tf32 hi
__device__ __align__(128) float    g_G [128 * 128 * 128];   // enemy table G[h][p][j]
__device__ __align__(128) float    g_Gf[128 * 128 * 16];    // friend table G[h][p][v]
__device__ __align__(128) float    g_lwF2[32768 * 16];      // friend lin1 @ lin2
__device__ __align__(128) float    g_tmp[256 * 128];        // enemy cb[o]*colsum
__device__ __align__(128) float    g_Sf[256 * 128];         // friend lw1 h-colsums
__device__ __align__(128) float    g_fconst[128];
__device__ __align__(128) float    g_tmpf[256 * 16];
__device__ __align__(128) float    g_fconst2[16];
__device__ __align__(128) float    g_Lmid[64 * 256];
__device__ __align__(128) float    g_Wsum[3 * 64 * 128];    // manip conv weight sums

// ---------------------------------------------------------------------------
// Helpers
// ---------------------------------------------------------------------------
__device__ __forceinline__ uint32_t f2tf32(float x) {
    uint32_t r;
    asm("cvt.rna.tf32.f32 %0, %1;" : "=r"(r) : "f"(x));
    return r;
}
__device__ __forceinline__ void mma8(float* c, const uint32_t* a, const uint32_t* b) {
    asm volatile(
        "mma.sync.aligned.m16n8k8.row.col.f32.tf32.tf32.f32 "
        "{%0,%1,%2,%3}, {%4,%5,%6,%7}, {%8,%9}, {%0,%1,%2,%3};"
        : "+f"(c[0]), "+f"(c[1]), "+f"(c[2]), "+f"(c[3])
        : "r"(a[0]), "r"(a[1]), "r"(a[2]), "r"(a[3]), "r"(b[0]), "r"(b[1]));
}
__device__ __forceinline__ void cp16(uint32_t saddr, const void* g) {
    asm volatile("cp.async.cg.shared.global [%0], [%1], 16;" :: "r"(saddr), "l"(g));
}
__device__ __forceinline__ void cp16z(uint32_t saddr, const void* g, int srcsz) {
    asm volatile("cp.async.cg.shared.global [%0], [%1], 16, %2;"
                 :: "r"(saddr), "l"(g), "r"(srcsz));
}
__device__ __forceinline__ void cp_commit() {
    asm volatile("cp.async.commit_group;");
}

// ===========================================================================
// LAYER 1: vmax (e+f) | lw column-sums (e+f) | prep (Lmid+Wsum) | lwf2
//   grid 3232 x 256   (all pure input consumers or input-only deps)
// ===========================================================================
__global__ void __launch_bounds__(256) stage1(
    const float* __restrict__ e_emb, const float* __restrict__ f_emb,
    const float* __restrict__ e_lw,  const float* __restrict__ e_cb,
    const float* __restrict__ f_lw,
    const float* __restrict__ mlw,   const float* __restrict__ mcw,
    const float* __restrict__ f_l2w)
{
    __shared__ float sred[256];
    __shared__ float lr[16][128];
    __shared__ float l2[128][16];
    int bx = blockIdx.x, t = threadIdx.x;

    if (bx < 512) {                       // ---- vmax both ----
        bool fr = bx >= 256;
        int idx = (fr ? bx - 256 : bx) * 256 + t;
        int c = idx >> 7, p = idx & 127;
        const float* emb = fr ? f_emb : e_emb;
        float v = 0.0f;
        if (p < 105) {
            int a = 0, rem = p;
            while (rem >= 14 - a) { rem -= 14 - a; a++; }
            int b = a + rem;
            v = fmaxf(emb[a * 512 + c], emb[b * 512 + c]);
        }
        (fr ? g_VmaxTf : g_VmaxT)[idx] = v;
    } else if (bx < 1024) {               // ---- lw column sums (e / f) ----
        bool fr = bx >= 768;
        int o = fr ? bx - 768 : bx - 512;
        const float* lw = fr ? f_lw : e_lw;
        int j = t & 127, hoff = t >> 7;
        float sum = 0.0f;
        for (int h2 = 0; h2 < 64; h2++) {
            int h = h2 * 2 + hoff;
            sum += lw[(size_t)(o * 128 + h) * 128 + j];
        }
        sred[t] = sum;
        __syncthreads();
        if (t < 128) {
            float s = sred[t] + sred[t + 128];
            if (fr) g_Sf[o * 128 + t] = s;
            else    g_tmp[o * 128 + t] = e_cb[o] * s;
        }
    } else if (bx < 1184) {               // ---- prep: Lmid + Wsum ----
        int idx = (bx - 1024) * 256 + t;  // < 40960
        if (idx < 16384) {
            int o = idx >> 8, j = idx & 255;
            float s = 0.0f;
            for (int h = 1; h <= 126; h++)
                s += mlw[(size_t)(o * 128 + h) * 256 + j];
            g_Lmid[idx] = s;
        } else {
            int k = idx - 16384;          // < 24576
            int row = k >> 7, i = k & 127;
            int g = row >> 6, o = row & 63;
            const float* wp = mcw + o * 1152 + i * 9;
            float w0 = wp[1], w1 = wp[4], w2 = wp[7];
            float ws = (g == 0) ? (w1 + w2) : ((g == 1) ? (w0 + w1 + w2) : (w0 + w1));
            g_Wsum[(g * 64 + o) * 128 + i] = ws;
        }
    } else {                              // ---- lwf2 ----
        int blk = bx - 1184;              // 0..2047
        for (int i = t; i < 2048; i += 256)
            lr[i >> 7][i & 127] = f_lw[(size_t)blk * 2048 + i];
        for (int i = t; i < 2048; i += 256) {
            int j = i >> 4, v = i & 15;
            l2[j][v] = (v < 14) ? f_l2w[j * 14 + v] : 0.0f;
        }
        __syncthreads();
        int r = t >> 4, v = t & 15;
        float acc = 0.0f;
#pragma unroll 8
        for (int j = 0; j < 128; j++)
            acc += lr[r][j] * l2[j][v];
        g_lwF2[(size_t)(blk * 16 + r) * 16 + v] = acc;
    }
}

// ===========================================================================
// LAYER 2: u_both (8 k/block) | lsum2 | fc2a
//   grid 209 x 256
// ===========================================================================
__global__ void __launch_bounds__(256) stage2(
    const float* __restrict__ e_cw, const float* __restrict__ f_cw,
    const float* __restrict__ e_lb,
    const float* __restrict__ f_l2w, const float* __restrict__ f_cb)
{
    __shared__ float Wcol[8][512];
    __shared__ float s2[256];
    int bx = blockIdx.x, t = threadIdx.x;

    if (bx < 192) {                       // ---- u for both branches, 8 k each ----
        bool fr = bx >= 96;
        const float* cw   = fr ? f_cw : e_cw;
        const float* vmax = fr ? g_VmaxTf : g_VmaxT;
        int kbase = (fr ? bx - 96 : bx) * 8;
        int tx = t & 127, tg = t >> 7;    // tg in {0,1}, 4 k each
        for (int i = t; i < 4096; i += 256) {
            int yy = i >> 9, c = i & 511;
            int ky = kbase + yy;
            Wcol[yy][c] = cw[(ky & 255) * 4608 + c * 9 + (ky >> 8) * 3 + 1];
        }
        __syncthreads();
        float acc[4] = {0.0f, 0.0f, 0.0f, 0.0f};
#pragma unroll 4
        for (int c = 0; c < 512; c++) {
            float v = vmax[c * 128 + tx];
#pragma unroll
            for (int i = 0; i < 4; i++)
                acc[i] += v * Wcol[tg * 4 + i][c];
        }
#pragma unroll
        for (int i = 0; i < 4; i++) {
            int addr = (kbase + tg * 4 + i) * 128 + tx;
            uint32_t hi = f2tf32(acc[i]);
            if (fr) {
                g_U2Tfhi[addr] = hi;
            } else {
                g_U2Thi[addr] = hi;
                g_U2Tlo[addr] = f2tf32(acc[i] - __uint_as_float(hi));
            }
        }
    } else if (bx == 192) {               // ---- lsum2 -> fconst ----
        int j = t & 127, half = t >> 7;
        float s = 0.0f;
        int o0 = half * 128;
        for (int o = o0; o < o0 + 128; o++) s += g_tmp[o * 128 + j];
        s2[t] = s;
        __syncthreads();
        if (t < 128) g_fconst[t] = e_lb[t] + s2[t] + s2[t + 128];
    } else {                              // ---- fc2a from Sf ----
        int blk = bx - 193;               // 0..15
        int o = blk * 16 + (t >> 4), v = t & 15;
        float acc = 0.0f;
        if (v < 14)
            for (int j = 0; j < 128; j++)
                acc += g_Sf[o * 128 + j] * f_l2w[j * 14 + v];
        g_tmpf[o * 16 + v] = f_cb[o] * acc;
    }
}

// ===========================================================================
// LAYER 3: ggemm_e (256 blk) | ggemm_f (128 blk) | fc2b (1 blk)
//   grid 385 x 256, dyn smem 44032 B  (unchanged from R8 — proven)
// ===========================================================================
#define ASTR 136
#define BSTR 72
#define AWORDS (16 * ASTR)               // 2176
#define BWORDS (16 * BSTR)               // 1152
#define AOFFALL (4 * AWORDS)             // 8704
#define SME_BYTES ((4 * AWORDS + 2 * BWORDS) * 4)   // 44032

__global__ void __launch_bounds__(256, 2) stage3(
    const float* __restrict__ e_lw,
    const float* __restrict__ f_lb, const float* __restrict__ f_l2w,
    const float* __restrict__ f_l2b)
{
    extern __shared__ uint32_t sm[];
    int bx = blockIdx.x, t = threadIdx.x;
    int lane = t & 31;
    int wid  = t >> 5;
    int gid  = lane >> 2;
    int tig  = lane & 3;
    uint32_t sbase = (uint32_t)__cvta_generic_to_shared(sm);

    if (bx < 256) {
        // ================= ggemm_e: 3xTF32, raw-B conversion =================
        int hh = bx >> 1, by = bx & 1;
        int wm = wid & 3, wn = wid >> 2;

        float acc[2][4][4];
#pragma unroll
        for (int i = 0; i < 2; i++)
#pragma unroll
            for (int j = 0; j < 4; j++)
#pragma unroll
                for (int q = 0; q < 4; q++) acc[i][j][q] = 0.0f;

        auto load_stage = [&](int s, int k0) {
#pragma unroll
            for (int pl = 0; pl < 2; pl++) {
#pragma unroll
                for (int q = 0; q < 2; q++) {
                    int c   = t * 2 + q;
                    int row = c >> 5;
                    int c4  = (c & 31) * 4;
                    uint32_t sa = sbase + (uint32_t)(((s * 2 + pl) * AWORDS + row * ASTR + c4) * 4);
                    const uint32_t* g = (pl ? g_U2Tlo : g_U2Thi) + (size_t)(k0 + row) * 128 + c4;
                    cp16(sa, g);
                }
            }
            {
                int row = t >> 4;
                int c4  = (t & 15) * 4;
                int k   = k0 + row;
                int tap = k >> 8, o = k & 255;
                int h   = hh + 1 - tap;
                int ok  = (h >= 0 && h < 128) ? 16 : 0;
                const float* g = e_lw + (ok ? ((size_t)(o * 128 + h) * 128 + by * 64 + c4) : 0);
                uint32_t sa = sbase + (uint32_t)((AOFFALL + s * BWORDS + row * BSTR + c4) * 4);
                cp16z(sa, g, ok);
            }
            cp_commit();
        };

        const int NIT = KTOT / 16;   // 48
        load_stage(0, 0);

        for (int it = 0; it < NIT; it++) {
            if (it + 1 < NIT) {
                load_stage((it + 1) & 1, (it + 1) * 16);
                asm volatile("cp.async.wait_group 1;");
            } else {
                asm volatile("cp.async.wait_group 0;");
            }
            __syncthreads();

            int s = it & 1;
            const uint32_t* A0 = sm + (s * 2 + 0) * AWORDS;
            const uint32_t* A1 = sm + (s * 2 + 1) * AWORDS;
            const float*    Br = (const float*)(sm + AOFFALL + s * BWORDS);

#pragma unroll
            for (int ks = 0; ks < 2; ks++) {
                int kr = ks * 8;
                uint32_t af[2][2][4];
#pragma unroll
                for (int mi = 0; mi < 2; mi++) {
                    int m = wm * 32 + mi * 16;
                    af[0][mi][0] = A0[(kr + tig) * ASTR + m + gid];
                    af[0][mi][1] = A0[(kr + tig) * ASTR + m + gid + 8];
                    af[0][mi][2] = A0[(kr + tig + 4) * ASTR + m + gid];
                    af[0][mi][3] = A0[(kr + tig + 4) * ASTR + m + gid + 8];
                    af[1][mi][0] = A1[(kr + tig) * ASTR + m + gid];
                    af[1][mi][1] = A1[(kr + tig) * ASTR + m + gid + 8];
                    af[1][mi][2] = A1[(kr + tig + 4) * ASTR + m + gid];
                    af[1][mi][3] = A1[(kr + tig + 4) * ASTR + m + gid + 8];
                }
#pragma unroll
                for (int nj = 0; nj < 4; nj++) {
                    int n = wn * 32 + nj * 8;
                    float v0 = Br[(kr + tig) * BSTR + n + gid];
                    float v1 = Br[(kr + tig + 4) * BSTR + n + gid];
                    uint32_t bh[2], bl[2];
                    bh[0] = f2tf32(v0); bl[0] = f2tf32(v0 - __uint_as_float(bh[0]));
                    bh[1] = f2tf32(v1); bl[1] = f2tf32(v1 - __uint_as_float(bh[1]));
#pragma unroll
                    for (int mi = 0; mi < 2; mi++) {
                        mma8(acc[mi][nj], af[0][mi], bh);
                        mma8(acc[mi][nj], af[0][mi], bl);
                        mma8(acc[mi][nj], af[1][mi], bh);
                    }
                }
            }
            __syncthreads();
        }

        float* gbase = g_G + (size_t)hh * (128 * 128);
#pragma unroll
        for (int mi = 0; mi < 2; mi++) {
            int m = wm * 32 + mi * 16 + gid;
#pragma unroll
            for (int nj = 0; nj < 4; nj++) {
                int n = by * 64 + wn * 32 + nj * 8 + 2 * tig;
                gbase[(size_t)m * 128 + n]           = acc[mi][nj][0];
                gbase[(size_t)m * 128 + n + 1]       = acc[mi][nj][1];
                gbase[(size_t)(m + 8) * 128 + n]     = acc[mi][nj][2];
                gbase[(size_t)(m + 8) * 128 + n + 1] = acc[mi][nj][3];
            }
        }
    } else if (bx < 384) {
        // ================= ggemm_f: 8 warps x 16 M-rows, single TF32 ==========
        int hh = bx - 256;
        int wm = wid;

        float acc[2][4];
#pragma unroll
        for (int j = 0; j < 2; j++)
#pragma unroll
            for (int q = 0; q < 4; q++) acc[j][q] = 0.0f;

        const int FB = 4352;

        auto load_stage = [&](int s, int k0) {
#pragma unroll
            for (int q = 0; q < 2; q++) {
                int c   = t * 2 + q;
                int row = c >> 5;
                int c4  = (c & 31) * 4;
                uint32_t sa = sbase + (uint32_t)((s * 2176 + row * 136 + c4) * 4);
                const uint32_t* g = g_U2Tfhi + (size_t)(k0 + row) * 128 + c4;
                cp16(sa, g);
            }
            if (t < 64) {
                int row = t >> 2;
                int c4  = (t & 3) * 4;
                int k   = k0 + row;
                int tap = k >> 8, o = k & 255;
                int h   = hh + 1 - tap;
                int ok  = (h >= 0 && h < 128) ? 16 : 0;
                const float* g = g_lwF2 + (ok ? ((size_t)(o * 128 + h) * 16 + c4) : 0);
                uint32_t sa = sbase + (uint32_t)((FB + s * 384 + row * 24 + c4) * 4);
                cp16z(sa, g, ok);
            }
            cp_commit();
        };

        const int NIT = KTOT / 16;
        load_stage(0, 0);

        for (int it = 0; it < NIT; it++) {
            if (it + 1 < NIT) {
                load_stage((it + 1) & 1, (it + 1) * 16);
                asm volatile("cp.async.wait_group 1;");
            } else {
                asm volatile("cp.async.wait_group 0;");
            }
            __syncthreads();
            int s = it & 1;
            const uint32_t* A  = sm + s * 2176;
            const float*    Br = (const float*)(sm + FB + s * 384);

#pragma unroll
            for (int ks = 0; ks < 2; ks++) {
                int kr = ks * 8;
                uint32_t af[4];
                int m = wm * 16;
                af[0] = A[(kr + tig) * 136 + m + gid];
                af[1] = A[(kr + tig) * 136 + m + gid + 8];
                af[2] = A[(kr + tig + 4) * 136 + m + gid];
                af[3] = A[(kr + tig + 4) * 136 + m + gid + 8];
#pragma unroll
                for (int nj = 0; nj < 2; nj++) {
                    int n = nj * 8;
                    uint32_t bf[2];
                    bf[0] = f2tf32(Br[(kr + tig) * 24 + n + gid]);
                    bf[1] = f2tf32(Br[(kr + tig + 4) * 24 + n + gid]);
                    mma8(acc[nj], af, bf);
                }
            }
            __syncthreads();
        }

        float* gbase = g_Gf + (size_t)hh * (128 * 16);
        int m = wm * 16 + gid;
#pragma unroll
        for (int nj = 0; nj < 2; nj++) {
            int n = nj * 8 + 2 * tig;
            gbase[m * 16 + n]           = acc[nj][0];
            gbase[m * 16 + n + 1]       = acc[nj][1];
            gbase[(m + 8) * 16 + n]     = acc[nj][2];
            gbase[(m + 8) * 16 + n + 1] = acc[nj][3];
        }
    } else {
        // ================= fc2b =================
        if (t < 16) {
            int v = t;
            float s = 0.0f;
            if (v < 14) {
                s = f_l2b[v];
                for (int j = 0; j < 128; j++) s += f_lb[j] * f_l2w[j * 14 + v];
            }
            for (int o = 0; o < 256; o++) s += g_tmpf[o * 16 + v];
            g_fconst2[v] = (v < 14) ? s : 0.0f;
        }
    }
}

// ===========================================================================
// LAYER 4: fused per-batch chain, cp.async smem-staged gathers
//   dyn smem 65536 B (G rows)
// ===========================================================================
#define FB_SMEM 65536

__global__ void __launch_bounds__(256) fused_batch(const int* __restrict__ x,
                                                   const float* __restrict__ mcb,
                                                   const float* __restrict__ mlw,
                                                   const float* __restrict__ mlb,
                                                   float* __restrict__ out)
{
    extern __shared__ float gbuf[];       // 128 rows x 128 floats (64 KB)
    __shared__ float eo[128];
    __shared__ float rr[192];
    __shared__ int   sp[128];
    __shared__ float red[128];
    __shared__ float part2[256];
    __shared__ int   tok[256];
    __shared__ float lg[16];
    int b = blockIdx.x, t = threadIdx.x;
    uint32_t sb = (uint32_t)__cvta_generic_to_shared(gbuf);

    // ---- enemy pair indices ----
    if (t < 128) {
        int t0 = x[b * 256 + 2 * t], t1 = x[b * 256 + 2 * t + 1];
        int a = min(t0, t1), c = max(t0, t1);
        sp[t] = a * 14 + c - ((a * (a + 1)) >> 1);
    }
    __syncthreads();

    // ---- stage all 128 G rows into smem (max-MLP burst) ----
#pragma unroll
    for (int it = 0; it < 16; it++) {
        int chunk = it * 256 + t;         // 0..4095, 16B each
        int h  = chunk >> 5;
        int c4 = (chunk & 31) * 4;
        cp16(sb + chunk * 16, g_G + (size_t)((h << 7) + sp[h]) * 128 + c4);
    }
    cp_commit();
    asm volatile("cp.async.wait_group 0;");
    __syncthreads();

    // ---- gather_e reduce from smem (same order as before) ----
    {
        int j = t & 127, half = t >> 7;
        float ps = 0.0f;
        int h0 = half * 64;
#pragma unroll 8
        for (int i = 0; i < 64; i++)
            ps += gbuf[(h0 + i) * 128 + j];
        part2[t] = ps;
    }
    __syncthreads();
    float fval = 0.0f;
    if (t < 128) { fval = g_fconst[t] + part2[t] + part2[t + 128]; red[t] = fval; }
    __syncthreads();
    for (int o = 64; o > 0; o >>= 1) { if (t < o) red[t] = fmaxf(red[t], red[t + o]); __syncthreads(); }
    float mx = red[0]; __syncthreads();
    float ev = 0.0f;
    if (t < 128) { ev = expf(fval - mx); red[t] = ev; }
    __syncthreads();
    for (int o = 64; o > 0; o >>= 1) { if (t < o) red[t] += red[t + o]; __syncthreads(); }
    if (t < 128) eo[t] = ev / red[0];
    __syncthreads();

    // ---- manip conv ----
    if (t < 192) {
        int g = t / 64, o = t % 64;
        float acc = mcb[o];
        const float* wrow = g_Wsum + (g * 64 + o) * 128;
#pragma unroll 8
        for (int i = 0; i < 128; i++)
            acc += eo[i] * wrow[i];
        rr[t] = fmaxf(acc, 0.0f);
    }
    __syncthreads();

    // ---- manip linear + token quantization ----
    {
        float mm = mlb[t];
#pragma unroll 4
        for (int o = 0; o < 64; o++) {
            mm += rr[o]       * mlw[(size_t)(o * 128) * 256 + t];
            mm += rr[64 + o]  * g_Lmid[o * 256 + t];
            mm += rr[128 + o] * mlw[(size_t)(o * 128 + 127) * 256 + t];
        }
        tok[t] = (int)(fmodf(floorf(fabsf(mm) * 100.0f), 14.0f));
    }
    __syncthreads();

    // ---- friend pair indices ----
    if (t < 128) {
        int t0 = tok[2 * t], t1 = tok[2 * t + 1];
        int a = min(t0, t1), c = max(t0, t1);
        sp[t] = a * 14 + c - ((a * (a + 1)) >> 1);
    }
    __syncthreads();

    // ---- stage Gf rows (8 KB) ----
#pragma unroll
    for (int it = 0; it < 2; it++) {
        int chunk = it * 256 + t;         // 0..511
        int h  = chunk >> 2;
        int c4 = (chunk & 3) * 4;
        cp16(sb + chunk * 16, g_Gf + (size_t)((h << 7) + sp[h]) * 16 + c4);
    }
    cp_commit();
    asm volatile("cp.async.wait_group 0;");
    __syncthreads();

    // ---- gather_f reduce ----
    if (t < 128) {
        int v = t & 15, hg = t >> 4;
        float ps = 0.0f;
#pragma unroll 4
        for (int i = 0; i < 16; i++)
            ps += gbuf[(hg * 16 + i) * 16 + v];
        part2[t] = ps;
    }
    __syncthreads();
    if (t < 16) {
        float s = g_fconst2[t];
        for (int g = 0; g < 8; g++) s += part2[g * 16 + t];
        lg[t] = s;
    }
    __syncthreads();
    if (t == 0) {
        float mx2 = lg[0];
        for (int q = 1; q < 14; q++) mx2 = fmaxf(mx2, lg[q]);
        float sum = 0.0f;
        for (int q = 0; q < 14; q++) { float e2 = expf(lg[q] - mx2); lg[q] = e2; sum += e2; }
        float inv = 1.0f / sum;
        for (int q = 0; q < 14; q++) out[b * 14 + q] = lg[q] * inv;
    }
}

// ---------------------------------------------------------------------------
// Launch: 4 layered launches
// ---------------------------------------------------------------------------
extern "C" void kernel_launch(void* const* d_in, const int* in_sizes, int n_in,
                              void* d_out, int out_size)
{
    const int*   x     = (const int*)  d_in[0];
    const float* e_emb = (const float*)d_in[1];
    const float* e_cw  = (const float*)d_in[2];
    const float* e_cb  = (const float*)d_in[3];
    const float* e_lw  = (const float*)d_in[4];
    const float* e_lb  = (const float*)d_in[5];
    // d_in[6] = rand_proj (dead: fog_of_war is provably identity)
    const float* m_cw  = (const float*)d_in[7];
    const float* m_cb  = (const float*)d_in[8];
    const float* m_lw  = (const float*)d_in[9];
    const float* m_lb  = (const float*)d_in[10];
    const float* f_emb = (const float*)d_in[11];
    const float* f_cw  = (const float*)d_in[12];
    const float* f_cb  = (const float*)d_in[13];
    const float* f_lw  = (const float*)d_in[14];
    const float* f_lb  = (const float*)d_in[15];
    const float* f_l2w = (const float*)d_in[16];
    const float* f_l2b = (const float*)d_in[17];
    float* out = (float*)d_out;

    cudaFuncSetAttribute(stage3, cudaFuncAttributeMaxDynamicSharedMemorySize, SME_BYTES);
    cudaFuncSetAttribute(fused_batch, cudaFuncAttributeMaxDynamicSharedMemorySize, FB_SMEM);

    stage1      <<<3232, 256>>>(e_emb, f_emb, e_lw, e_cb, f_lw, m_lw, m_cw, f_l2w);
    stage2      <<<209, 256>>>(e_cw, f_cw, e_lb, f_l2w, f_cb);
    stage3      <<<385, 256, SME_BYTES>>>(e_lw, f_lb, f_l2w, f_l2b);
    fused_batch <<<BB, 256, FB_SMEM>>>(x, m_cb, m_lw, m_lb, out);
}

// round 10
// speedup vs baseline: 1.0452x; 1.0452x over previous
#include <cuda_runtime.h>
#include <math.h>
#include <stdint.h>

#define BB    256
#define KTOT  768        // 3 taps * 256 conv-out channels

// ---------------------------------------------------------------------------
// Static device scratch
// ---------------------------------------------------------------------------
__device__ __align__(128) float    g_VmaxT [512 * 128];     // enemy pairwise-max emb [c][p]
__device__ __align__(128) float    g_VmaxTf[512 * 128];     // friend
__device__ __align__(128) uint32_t g_U2Thi [KTOT * 128];    // enemy U tf32 hi
__device__ __align__(128) uint32_t g_U2Tlo [KTOT * 128];    // enemy U tf32 lo
__device__ __align__(128) uint32_t g_U2Tfhi[KTOT * 128];    // friend U tf32 hi
__device__ __align__(128) float    g_G [128 * 128 * 128];   // enemy table G[h][p][j]
__device__ __align__(128) float    g_Gf[128 * 128 * 16];    // friend table G[h][p][v]
__device__ __align__(128) float    g_lwF2[32768 * 16];      // friend lin1 @ lin2
__device__ __align__(128) float    g_tmp[256 * 128];        // enemy cb[o]*colsum
__device__ __align__(128) float    g_Sf[256 * 128];         // friend lw1 h-colsums
__device__ __align__(128) float    g_fconst[128];
__device__ __align__(128) float    g_tmpf[256 * 16];
__device__ __align__(128) float    g_fconst2[16];
__device__ __align__(128) float    g_Lmid[64 * 256];
__device__ __align__(128) float    g_Wsum[3 * 64 * 128];    // manip conv weight sums

// ---------------------------------------------------------------------------
// Helpers
// ---------------------------------------------------------------------------
__device__ __forceinline__ uint32_t f2tf32(float x) {
    uint32_t r;
    asm("cvt.rna.tf32.f32 %0, %1;" : "=r"(r) : "f"(x));
    return r;
}
__device__ __forceinline__ void mma8(float* c, const uint32_t* a, const uint32_t* b) {
    asm volatile(
        "mma.sync.aligned.m16n8k8.row.col.f32.tf32.tf32.f32 "
        "{%0,%1,%2,%3}, {%4,%5,%6,%7}, {%8,%9}, {%0,%1,%2,%3};"
        : "+f"(c[0]), "+f"(c[1]), "+f"(c[2]), "+f"(c[3])
        : "r"(a[0]), "r"(a[1]), "r"(a[2]), "r"(a[3]), "r"(b[0]), "r"(b[1]));
}
__device__ __forceinline__ void cp16(uint32_t saddr, const void* g) {
    asm volatile("cp.async.cg.shared.global [%0], [%1], 16;" :: "r"(saddr), "l"(g));
}
__device__ __forceinline__ void cp16z(uint32_t saddr, const void* g, int srcsz) {
    asm volatile("cp.async.cg.shared.global [%0], [%1], 16, %2;"
                 :: "r"(saddr), "l"(g), "r"(srcsz));
}
__device__ __forceinline__ void cp_commit() {
    asm volatile("cp.async.commit_group;");
}

// ===========================================================================
// LAYER 1: vmax (e+f) | lw column-sums (e+f) | prep (Lmid + Wsum)
//   grid 1184 x 256   (R8 layout — proven)
// ===========================================================================
__global__ void __launch_bounds__(256) stage1(
    const float* __restrict__ e_emb, const float* __restrict__ f_emb,
    const float* __restrict__ e_lw,  const float* __restrict__ e_cb,
    const float* __restrict__ f_lw,
    const float* __restrict__ mlw,   const float* __restrict__ mcw)
{
    __shared__ float sred[256];
    int bx = blockIdx.x, t = threadIdx.x;

    if (bx < 512) {                       // ---- vmax both ----
        bool fr = bx >= 256;
        int idx = (fr ? bx - 256 : bx) * 256 + t;
        int c = idx >> 7, p = idx & 127;
        const float* emb = fr ? f_emb : e_emb;
        float v = 0.0f;
        if (p < 105) {
            int a = 0, rem = p;
            while (rem >= 14 - a) { rem -= 14 - a; a++; }
            int b = a + rem;
            v = fmaxf(emb[a * 512 + c], emb[b * 512 + c]);
        }
        (fr ? g_VmaxTf : g_VmaxT)[idx] = v;
    } else if (bx < 1024) {               // ---- lw column sums (e / f) ----
        bool fr = bx >= 768;
        int o = fr ? bx - 768 : bx - 512;
        const float* lw = fr ? f_lw : e_lw;
        int j = t & 127, hoff = t >> 7;
        float sum = 0.0f;
        for (int h2 = 0; h2 < 64; h2++) {
            int h = h2 * 2 + hoff;
            sum += lw[(size_t)(o * 128 + h) * 128 + j];
        }
        sred[t] = sum;
        __syncthreads();
        if (t < 128) {
            float s = sred[t] + sred[t + 128];
            if (fr) g_Sf[o * 128 + t] = s;
            else    g_tmp[o * 128 + t] = e_cb[o] * s;
        }
    } else {                              // ---- prep: Lmid + Wsum ----
        int idx = (bx - 1024) * 256 + t;  // < 40960
        if (idx < 16384) {
            int o = idx >> 8, j = idx & 255;
            float s = 0.0f;
#pragma unroll 6
            for (int h = 1; h <= 126; h++)
                s += mlw[(size_t)(o * 128 + h) * 256 + j];
            g_Lmid[idx] = s;
        } else {
            int k = idx - 16384;          // < 24576
            int row = k >> 7, i = k & 127;
            int g = row >> 6, o = row & 63;
            const float* wp = mcw + o * 1152 + i * 9;
            float w0 = wp[1], w1 = wp[4], w2 = wp[7];
            float ws = (g == 0) ? (w1 + w2) : ((g == 1) ? (w0 + w1 + w2) : (w0 + w1));
            g_Wsum[(g * 64 + o) * 128 + i] = ws;
        }
    }
}

// ===========================================================================
// LAYER 2: u_both (8 k/block, 192 blk) | lsum2 (1) | lwf2 (2048) | fc2a (16)
//   grid 2257 x 256   (lwf2 fills SMs behind the long u blocks)
// ===========================================================================
__global__ void __launch_bounds__(256) stage2(
    const float* __restrict__ e_cw, const float* __restrict__ f_cw,
    const float* __restrict__ e_lb,
    const float* __restrict__ f_lw1, const float* __restrict__ f_l2w,
    const float* __restrict__ f_cb)
{
    __shared__ float Wcol[8][512];
    __shared__ float lr[16][128];
    __shared__ float l2[128][16];
    __shared__ float s2[256];
    int bx = blockIdx.x, t = threadIdx.x;

    if (bx < 192) {                       // ---- u for both branches, 8 k each ----
        bool fr = bx >= 96;
        const float* cw   = fr ? f_cw : e_cw;
        const float* vmax = fr ? g_VmaxTf : g_VmaxT;
        int kbase = (fr ? bx - 96 : bx) * 8;
        int tx = t & 127, tg = t >> 7;    // tg in {0,1}, 4 k each
        for (int i = t; i < 4096; i += 256) {
            int yy = i >> 9, c = i & 511;
            int ky = kbase + yy;
            Wcol[yy][c] = cw[(ky & 255) * 4608 + c * 9 + (ky >> 8) * 3 + 1];
        }
        __syncthreads();
        float acc[4] = {0.0f, 0.0f, 0.0f, 0.0f};
#pragma unroll 4
        for (int c = 0; c < 512; c++) {
            float v = vmax[c * 128 + tx];
#pragma unroll
            for (int i = 0; i < 4; i++)
                acc[i] += v * Wcol[tg * 4 + i][c];
        }
#pragma unroll
        for (int i = 0; i < 4; i++) {
            int addr = (kbase + tg * 4 + i) * 128 + tx;
            uint32_t hi = f2tf32(acc[i]);
            if (fr) {
                g_U2Tfhi[addr] = hi;
            } else {
                g_U2Thi[addr] = hi;
                g_U2Tlo[addr] = f2tf32(acc[i] - __uint_as_float(hi));
            }
        }
    } else if (bx == 192) {               // ---- lsum2 -> fconst ----
        int j = t & 127, half = t >> 7;
        float s = 0.0f;
        int o0 = half * 128;
        for (int o = o0; o < o0 + 128; o++) s += g_tmp[o * 128 + j];
        s2[t] = s;
        __syncthreads();
        if (t < 128) g_fconst[t] = e_lb[t] + s2[t] + s2[t + 128];
    } else if (bx < 2241) {               // ---- lwf2 ----
        int blk = bx - 193;               // 0..2047
        for (int i = t; i < 2048; i += 256)
            lr[i >> 7][i & 127] = f_lw1[(size_t)blk * 2048 + i];
        for (int i = t; i < 2048; i += 256) {
            int j = i >> 4, v = i & 15;
            l2[j][v] = (v < 14) ? f_l2w[j * 14 + v] : 0.0f;
        }
        __syncthreads();
        int r = t >> 4, v = t & 15;
        float acc = 0.0f;
#pragma unroll 8
        for (int j = 0; j < 128; j++)
            acc += lr[r][j] * l2[j][v];
        g_lwF2[(size_t)(blk * 16 + r) * 16 + v] = acc;
    } else {                              // ---- fc2a from Sf ----
        int blk = bx - 2241;              // 0..15
        int o = blk * 16 + (t >> 4), v = t & 15;
        float acc = 0.0f;
        if (v < 14)
            for (int j = 0; j < 128; j++)
                acc += g_Sf[o * 128 + j] * f_l2w[j * 14 + v];
        g_tmpf[o * 16 + v] = f_cb[o] * acc;
    }
}

// ===========================================================================
// LAYER 3: ggemm_e (256 blk) | ggemm_f (128 blk) | fc2b (1 blk)
//   grid 385 x 256, dyn smem 44032 B  (unchanged from R8 — proven)
// ===========================================================================
#define ASTR 136
#define BSTR 72
#define AWORDS (16 * ASTR)               // 2176
#define BWORDS (16 * BSTR)               // 1152
#define AOFFALL (4 * AWORDS)             // 8704
#define SME_BYTES ((4 * AWORDS + 2 * BWORDS) * 4)   // 44032

__global__ void __launch_bounds__(256, 2) stage3(
    const float* __restrict__ e_lw,
    const float* __restrict__ f_lb, const float* __restrict__ f_l2w,
    const float* __restrict__ f_l2b)
{
    extern __shared__ uint32_t sm[];
    int bx = blockIdx.x, t = threadIdx.x;
    int lane = t & 31;
    int wid  = t >> 5;
    int gid  = lane >> 2;
    int tig  = lane & 3;
    uint32_t sbase = (uint32_t)__cvta_generic_to_shared(sm);

    if (bx < 256) {
        // ================= ggemm_e: 3xTF32, raw-B conversion =================
        int hh = bx >> 1, by = bx & 1;
        int wm = wid & 3, wn = wid >> 2;

        float acc[2][4][4];
#pragma unroll
        for (int i = 0; i < 2; i++)
#pragma unroll
            for (int j = 0; j < 4; j++)
#pragma unroll
                for (int q = 0; q < 4; q++) acc[i][j][q] = 0.0f;

        auto load_stage = [&](int s, int k0) {
#pragma unroll
            for (int pl = 0; pl < 2; pl++) {
#pragma unroll
                for (int q = 0; q < 2; q++) {
                    int c   = t * 2 + q;
                    int row = c >> 5;
                    int c4  = (c & 31) * 4;
                    uint32_t sa = sbase + (uint32_t)(((s * 2 + pl) * AWORDS + row * ASTR + c4) * 4);
                    const uint32_t* g = (pl ? g_U2Tlo : g_U2Thi) + (size_t)(k0 + row) * 128 + c4;
                    cp16(sa, g);
                }
            }
            {
                int row = t >> 4;
                int c4  = (t & 15) * 4;
                int k   = k0 + row;
                int tap = k >> 8, o = k & 255;
                int h   = hh + 1 - tap;
                int ok  = (h >= 0 && h < 128) ? 16 : 0;
                const float* g = e_lw + (ok ? ((size_t)(o * 128 + h) * 128 + by * 64 + c4) : 0);
                uint32_t sa = sbase + (uint32_t)((AOFFALL + s * BWORDS + row * BSTR + c4) * 4);
                cp16z(sa, g, ok);
            }
            cp_commit();
        };

        const int NIT = KTOT / 16;   // 48
        load_stage(0, 0);

        for (int it = 0; it < NIT; it++) {
            if (it + 1 < NIT) {
                load_stage((it + 1) & 1, (it + 1) * 16);
                asm volatile("cp.async.wait_group 1;");
            } else {
                asm volatile("cp.async.wait_group 0;");
            }
            __syncthreads();

            int s = it & 1;
            const uint32_t* A0 = sm + (s * 2 + 0) * AWORDS;
            const uint32_t* A1 = sm + (s * 2 + 1) * AWORDS;
            const float*    Br = (const float*)(sm + AOFFALL + s * BWORDS);

#pragma unroll
            for (int ks = 0; ks < 2; ks++) {
                int kr = ks * 8;
                uint32_t af[2][2][4];
#pragma unroll
                for (int mi = 0; mi < 2; mi++) {
                    int m = wm * 32 + mi * 16;
                    af[0][mi][0] = A0[(kr + tig) * ASTR + m + gid];
                    af[0][mi][1] = A0[(kr + tig) * ASTR + m + gid + 8];
                    af[0][mi][2] = A0[(kr + tig + 4) * ASTR + m + gid];
                    af[0][mi][3] = A0[(kr + tig + 4) * ASTR + m + gid + 8];
                    af[1][mi][0] = A1[(kr + tig) * ASTR + m + gid];
                    af[1][mi][1] = A1[(kr + tig) * ASTR + m + gid + 8];
                    af[1][mi][2] = A1[(kr + tig + 4) * ASTR + m + gid];
                    af[1][mi][3] = A1[(kr + tig + 4) * ASTR + m + gid + 8];
                }
#pragma unroll
                for (int nj = 0; nj < 4; nj++) {
                    int n = wn * 32 + nj * 8;
                    float v0 = Br[(kr + tig) * BSTR + n + gid];
                    float v1 = Br[(kr + tig + 4) * BSTR + n + gid];
                    uint32_t bh[2], bl[2];
                    bh[0] = f2tf32(v0); bl[0] = f2tf32(v0 - __uint_as_float(bh[0]));
                    bh[1] = f2tf32(v1); bl[1] = f2tf32(v1 - __uint_as_float(bh[1]));
#pragma unroll
                    for (int mi = 0; mi < 2; mi++) {
                        mma8(acc[mi][nj], af[0][mi], bh);
                        mma8(acc[mi][nj], af[0][mi], bl);
                        mma8(acc[mi][nj], af[1][mi], bh);
                    }
                }
            }
            __syncthreads();
        }

        float* gbase = g_G + (size_t)hh * (128 * 128);
#pragma unroll
        for (int mi = 0; mi < 2; mi++) {
            int m = wm * 32 + mi * 16 + gid;
#pragma unroll
            for (int nj = 0; nj < 4; nj++) {
                int n = by * 64 + wn * 32 + nj * 8 + 2 * tig;
                gbase[(size_t)m * 128 + n]           = acc[mi][nj][0];
                gbase[(size_t)m * 128 + n + 1]       = acc[mi][nj][1];
                gbase[(size_t)(m + 8) * 128 + n]     = acc[mi][nj][2];
                gbase[(size_t)(m + 8) * 128 + n + 1] = acc[mi][nj][3];
            }
        }
    } else if (bx < 384) {
        // ================= ggemm_f: 8 warps x 16 M-rows, single TF32 ==========
        int hh = bx - 256;
        int wm = wid;

        float acc[2][4];
#pragma unroll
        for (int j = 0; j < 2; j++)
#pragma unroll
            for (int q = 0; q < 4; q++) acc[j][q] = 0.0f;

        const int FB = 4352;

        auto load_stage = [&](int s, int k0) {
#pragma unroll
            for (int q = 0; q < 2; q++) {
                int c   = t * 2 + q;
                int row = c >> 5;
                int c4  = (c & 31) * 4;
                uint32_t sa = sbase + (uint32_t)((s * 2176 + row * 136 + c4) * 4);
                const uint32_t* g = g_U2Tfhi + (size_t)(k0 + row) * 128 + c4;
                cp16(sa, g);
            }
            if (t < 64) {
                int row = t >> 2;
                int c4  = (t & 3) * 4;
                int k   = k0 + row;
                int tap = k >> 8, o = k & 255;
                int h   = hh + 1 - tap;
                int ok  = (h >= 0 && h < 128) ? 16 : 0;
                const float* g = g_lwF2 + (ok ? ((size_t)(o * 128 + h) * 16 + c4) : 0);
                uint32_t sa = sbase + (uint32_t)((FB + s * 384 + row * 24 + c4) * 4);
                cp16z(sa, g, ok);
            }
            cp_commit();
        };

        const int NIT = KTOT / 16;
        load_stage(0, 0);

        for (int it = 0; it < NIT; it++) {
            if (it + 1 < NIT) {
                load_stage((it + 1) & 1, (it + 1) * 16);
                asm volatile("cp.async.wait_group 1;");
            } else {
                asm volatile("cp.async.wait_group 0;");
            }
            __syncthreads();
            int s = it & 1;
            const uint32_t* A  = sm + s * 2176;
            const float*    Br = (const float*)(sm + FB + s * 384);

#pragma unroll
            for (int ks = 0; ks < 2; ks++) {
                int kr = ks * 8;
                uint32_t af[4];
                int m = wm * 16;
                af[0] = A[(kr + tig) * 136 + m + gid];
                af[1] = A[(kr + tig) * 136 + m + gid + 8];
                af[2] = A[(kr + tig + 4) * 136 + m + gid];
                af[3] = A[(kr + tig + 4) * 136 + m + gid + 8];
#pragma unroll
                for (int nj = 0; nj < 2; nj++) {
                    int n = nj * 8;
                    uint32_t bf[2];
                    bf[0] = f2tf32(Br[(kr + tig) * 24 + n + gid]);
                    bf[1] = f2tf32(Br[(kr + tig + 4) * 24 + n + gid]);
                    mma8(acc[nj], af, bf);
                }
            }
            __syncthreads();
        }

        float* gbase = g_Gf + (size_t)hh * (128 * 16);
        int m = wm * 16 + gid;
#pragma unroll
        for (int nj = 0; nj < 2; nj++) {
            int n = nj * 8 + 2 * tig;
            gbase[m * 16 + n]           = acc[nj][0];
            gbase[m * 16 + n + 1]       = acc[nj][1];
            gbase[(m + 8) * 16 + n]     = acc[nj][2];
            gbase[(m + 8) * 16 + n + 1] = acc[nj][3];
        }
    } else {
        // ================= fc2b =================
        if (t < 16) {
            int v = t;
            float s = 0.0f;
            if (v < 14) {
                s = f_l2b[v];
                for (int j = 0; j < 128; j++) s += f_lb[j] * f_l2w[j * 14 + v];
            }
            for (int o = 0; o < 256; o++) s += g_tmpf[o * 16 + v];
            g_fconst2[v] = (v < 14) ? s : 0.0f;
        }
    }
}

// ===========================================================================
// LAYER 4: fused per-batch chain, cp.async smem-staged gathers (R9 — proven)
//   dyn smem 65536 B
// ===========================================================================
#define FB_SMEM 65536

__global__ void __launch_bounds__(256) fused_batch(const int* __restrict__ x,
                                                   const float* __restrict__ mcb,
                                                   const float* __restrict__ mlw,
                                                   const float* __restrict__ mlb,
                                                   float* __restrict__ out)
{
    extern __shared__ float gbuf[];       // 128 rows x 128 floats (64 KB)
    __shared__ float eo[128];
    __shared__ float rr[192];
    __shared__ int   sp[128];
    __shared__ float red[128];
    __shared__ float part2[256];
    __shared__ int   tok[256];
    __shared__ float lg[16];
    int b = blockIdx.x, t = threadIdx.x;
    uint32_t sb = (uint32_t)__cvta_generic_to_shared(gbuf);

    if (t < 128) {
        int t0 = x[b * 256 + 2 * t], t1 = x[b * 256 + 2 * t + 1];
        int a = min(t0, t1), c = max(t0, t1);
        sp[t] = a * 14 + c - ((a * (a + 1)) >> 1);
    }
    __syncthreads();

#pragma unroll
    for (int it = 0; it < 16; it++) {
        int chunk = it * 256 + t;         // 0..4095, 16B each
        int h  = chunk >> 5;
        int c4 = (chunk & 31) * 4;
        cp16(sb + chunk * 16, g_G + (size_t)((h << 7) + sp[h]) * 128 + c4);
    }
    cp_commit();
    asm volatile("cp.async.wait_group 0;");
    __syncthreads();

    {
        int j = t & 127, half = t >> 7;
        float ps = 0.0f;
        int h0 = half * 64;
#pragma unroll 8
        for (int i = 0; i < 64; i++)
            ps += gbuf[(h0 + i) * 128 + j];
        part2[t] = ps;
    }
    __syncthreads();
    float fval = 0.0f;
    if (t < 128) { fval = g_fconst[t] + part2[t] + part2[t + 128]; red[t] = fval; }
    __syncthreads();
    for (int o = 64; o > 0; o >>= 1) { if (t < o) red[t] = fmaxf(red[t], red[t + o]); __syncthreads(); }
    float mx = red[0]; __syncthreads();
    float ev = 0.0f;
    if (t < 128) { ev = expf(fval - mx); red[t] = ev; }
    __syncthreads();
    for (int o = 64; o > 0; o >>= 1) { if (t < o) red[t] += red[t + o]; __syncthreads(); }
    if (t < 128) eo[t] = ev / red[0];
    __syncthreads();

    if (t < 192) {
        int g = t / 64, o = t % 64;
        float acc = mcb[o];
        const float* wrow = g_Wsum + (g * 64 + o) * 128;
#pragma unroll 8
        for (int i = 0; i < 128; i++)
            acc += eo[i] * wrow[i];
        rr[t] = fmaxf(acc, 0.0f);
    }
    __syncthreads();

    {
        float mm = mlb[t];
#pragma unroll 4
        for (int o = 0; o < 64; o++) {
            mm += rr[o]       * mlw[(size_t)(o * 128) * 256 + t];
            mm += rr[64 + o]  * g_Lmid[o * 256 + t];
            mm += rr[128 + o] * mlw[(size_t)(o * 128 + 127) * 256 + t];
        }
        tok[t] = (int)(fmodf(floorf(fabsf(mm) * 100.0f), 14.0f));
    }
    __syncthreads();

    if (t < 128) {
        int t0 = tok[2 * t], t1 = tok[2 * t + 1];
        int a = min(t0, t1), c = max(t0, t1);
        sp[t] = a * 14 + c - ((a * (a + 1)) >> 1);
    }
    __syncthreads();

#pragma unroll
    for (int it = 0; it < 2; it++) {
        int chunk = it * 256 + t;         // 0..511
        int h  = chunk >> 2;
        int c4 = (chunk & 3) * 4;
        cp16(sb + chunk * 16, g_Gf + (size_t)((h << 7) + sp[h]) * 16 + c4);
    }
    cp_commit();
    asm volatile("cp.async.wait_group 0;");
    __syncthreads();

    if (t < 128) {
        int v = t & 15, hg = t >> 4;
        float ps = 0.0f;
#pragma unroll 4
        for (int i = 0; i < 16; i++)
            ps += gbuf[(hg * 16 + i) * 16 + v];
        part2[t] = ps;
    }
    __syncthreads();
    if (t < 16) {
        float s = g_fconst2[t];
        for (int g = 0; g < 8; g++) s += part2[g * 16 + t];
        lg[t] = s;
    }
    __syncthreads();
    if (t == 0) {
        float mx2 = lg[0];
        for (int q = 1; q < 14; q++) mx2 = fmaxf(mx2, lg[q]);
        float sum = 0.0f;
        for (int q = 0; q < 14; q++) { float e2 = expf(lg[q] - mx2); lg[q] = e2; sum += e2; }
        float inv = 1.0f / sum;
        for (int q = 0; q < 14; q++) out[b * 14 + q] = lg[q] * inv;
    }
}

// ---------------------------------------------------------------------------
// Launch: 4 layered launches
// ---------------------------------------------------------------------------
extern "C" void kernel_launch(void* const* d_in, const int* in_sizes, int n_in,
                              void* d_out, int out_size)
{
    const int*   x     = (const int*)  d_in[0];
    const float* e_emb = (const float*)d_in[1];
    const float* e_cw  = (const float*)d_in[2];
    const float* e_cb  = (const float*)d_in[3];
    const float* e_lw  = (const float*)d_in[4];
    const float* e_lb  = (const float*)d_in[5];
    // d_in[6] = rand_proj (dead: fog_of_war is provably identity)
    const float* m_cw  = (const float*)d_in[7];
    const float* m_cb  = (const float*)d_in[8];
    const float* m_lw  = (const float*)d_in[9];
    const float* m_lb  = (const float*)d_in[10];
    const float* f_emb = (const float*)d_in[11];
    const float* f_cw  = (const float*)d_in[12];
    const float* f_cb  = (const float*)d_in[13];
    const float* f_lw  = (const float*)d_in[14];
    const float* f_lb  = (const float*)d_in[15];
    const float* f_l2w = (const float*)d_in[16];
    const float* f_l2b = (const float*)d_in[17];
    float* out = (float*)d_out;

    cudaFuncSetAttribute(stage3, cudaFuncAttributeMaxDynamicSharedMemorySize, SME_BYTES);
    cudaFuncSetAttribute(fused_batch, cudaFuncAttributeMaxDynamicSharedMemorySize, FB_SMEM);

    stage1      <<<1184, 256>>>(e_emb, f_emb, e_lw, e_cb, f_lw, m_lw, m_cw);
    stage2      <<<2257, 256>>>(e_cw, f_cw, e_lb, f_lw, f_l2w, f_cb);
    stage3      <<<385, 256, SME_BYTES>>>(e_lw, f_lb, f_l2w, f_l2b);
    fused_batch <<<BB, 256, FB_SMEM>>>(x, m_cb, m_lw, m_lb, out);
}

// round 11
// speedup vs baseline: 1.0791x; 1.0325x over previous
#include <cuda_runtime.h>
#include <math.h>
#include <stdint.h>

#define BB    256
#define KTOT  768        // 3 taps * 256 conv-out channels

// ---------------------------------------------------------------------------
// Static device scratch
// ---------------------------------------------------------------------------
__device__ __align__(128) float    g_VmaxT [512 * 128];     // enemy pairwise-max emb [c][p]
__device__ __align__(128) float    g_VmaxTf[512 * 128];     // friend
__device__ __align__(128) uint32_t g_U2Thi [KTOT * 128];    // enemy U tf32 hi
__device__ __align__(128) uint32_t g_U2Tlo [KTOT * 128];    // enemy U tf32 lo
__device__ __align__(128) uint32_t g_U2Tfhi[KTOT * 128];    // friend U tf32 hi
__device__ __align__(128) float    g_G [128 * 128 * 128];   // enemy table G[h][p][j]
__device__ __align__(128) float    g_Gf[128 * 128 * 16];    // friend table G[h][p][v]
__device__ __align__(128) float    g_lwF2[32768 * 16];      // friend lin1 @ lin2
__device__ __align__(128) float    g_tmp[256 * 128];        // enemy cb[o]*colsum
__device__ __align__(128) float    g_Sf[256 * 128];         // friend lw1 h-colsums
__device__ __align__(128) float    g_fconst[128];
__device__ __align__(128) float    g_tmpf[256 * 16];
__device__ __align__(128) float    g_fconst2[16];
__device__ __align__(128) float    g_Lmid[64 * 256];
__device__ __align__(128) float    g_Wsum[3 * 64 * 128];    // manip conv weight sums

// ---------------------------------------------------------------------------
// Helpers
// ---------------------------------------------------------------------------
__device__ __forceinline__ uint32_t f2tf32(float x) {
    uint32_t r;
    asm("cvt.rna.tf32.f32 %0, %1;" : "=r"(r) : "f"(x));
    return r;
}
__device__ __forceinline__ void mma8(float* c, const uint32_t* a, const uint32_t* b) {
    asm volatile(
        "mma.sync.aligned.m16n8k8.row.col.f32.tf32.tf32.f32 "
        "{%0,%1,%2,%3}, {%4,%5,%6,%7}, {%8,%9}, {%0,%1,%2,%3};"
        : "+f"(c[0]), "+f"(c[1]), "+f"(c[2]), "+f"(c[3])
        : "r"(a[0]), "r"(a[1]), "r"(a[2]), "r"(a[3]), "r"(b[0]), "r"(b[1]));
}
__device__ __forceinline__ void cp16(uint32_t saddr, const void* g) {
    asm volatile("cp.async.cg.shared.global [%0], [%1], 16;" :: "r"(saddr), "l"(g));
}
__device__ __forceinline__ void cp16z(uint32_t saddr, const void* g, int srcsz) {
    asm volatile("cp.async.cg.shared.global [%0], [%1], 16, %2;"
                 :: "r"(saddr), "l"(g), "r"(srcsz));
}
__device__ __forceinline__ void cp_commit() {
    asm volatile("cp.async.commit_group;");
}

// ===========================================================================
// LAYER 1: vmax (e+f) | lw column-sums (e+f) | prep (Lmid + Wsum)
//   grid 1184 x 256   (R8 exact — proven 155.6)
// ===========================================================================
__global__ void __launch_bounds__(256) stage1(
    const float* __restrict__ e_emb, const float* __restrict__ f_emb,
    const float* __restrict__ e_lw,  const float* __restrict__ e_cb,
    const float* __restrict__ f_lw,
    const float* __restrict__ mlw,   const float* __restrict__ mcw)
{
    __shared__ float sred[256];
    int bx = blockIdx.x, t = threadIdx.x;

    if (bx < 512) {                       // ---- vmax both ----
        bool fr = bx >= 256;
        int idx = (fr ? bx - 256 : bx) * 256 + t;
        int c = idx >> 7, p = idx & 127;
        const float* emb = fr ? f_emb : e_emb;
        float v = 0.0f;
        if (p < 105) {
            int a = 0, rem = p;
            while (rem >= 14 - a) { rem -= 14 - a; a++; }
            int b = a + rem;
            v = fmaxf(emb[a * 512 + c], emb[b * 512 + c]);
        }
        (fr ? g_VmaxTf : g_VmaxT)[idx] = v;
    } else if (bx < 1024) {               // ---- lw column sums (e / f) ----
        bool fr = bx >= 768;
        int o = fr ? bx - 768 : bx - 512;
        const float* lw = fr ? f_lw : e_lw;
        int j = t & 127, hoff = t >> 7;
        float sum = 0.0f;
        for (int h2 = 0; h2 < 64; h2++) {
            int h = h2 * 2 + hoff;
            sum += lw[(size_t)(o * 128 + h) * 128 + j];
        }
        sred[t] = sum;
        __syncthreads();
        if (t < 128) {
            float s = sred[t] + sred[t + 128];
            if (fr) g_Sf[o * 128 + t] = s;
            else    g_tmp[o * 128 + t] = e_cb[o] * s;
        }
    } else {                              // ---- prep: Lmid + Wsum ----
        int idx = (bx - 1024) * 256 + t;  // < 40960
        if (idx < 16384) {
            int o = idx >> 8, j = idx & 255;
            float s = 0.0f;
            for (int h = 1; h <= 126; h++)
                s += mlw[(size_t)(o * 128 + h) * 256 + j];
            g_Lmid[idx] = s;
        } else {
            int k = idx - 16384;          // < 24576
            int row = k >> 7, i = k & 127;
            int g = row >> 6, o = row & 63;
            const float* wp = mcw + o * 1152 + i * 9;
            float w0 = wp[1], w1 = wp[4], w2 = wp[7];
            float ws = (g == 0) ? (w1 + w2) : ((g == 1) ? (w0 + w1 + w2) : (w0 + w1));
            g_Wsum[(g * 64 + o) * 128 + i] = ws;
        }
    }
}

// ===========================================================================
// LAYER 2: u_both (2 k/block, 768 blk) | lsum2 | lwf2 (2048) | fc2a (16)
//   grid 2833 x 256   (R8 exact — proven)
// ===========================================================================
__global__ void __launch_bounds__(256) stage2(
    const float* __restrict__ e_cw, const float* __restrict__ f_cw,
    const float* __restrict__ e_lb,
    const float* __restrict__ f_lw1, const float* __restrict__ f_l2w,
    const float* __restrict__ f_cb)
{
    __shared__ float Wcol[2][512];
    __shared__ float lr[16][128];
    __shared__ float l2[128][16];
    __shared__ float s2[256];
    int bx = blockIdx.x, t = threadIdx.x;

    if (bx < 768) {                       // ---- u for both branches ----
        bool fr = bx >= 384;
        const float* cw   = fr ? f_cw : e_cw;
        const float* vmax = fr ? g_VmaxTf : g_VmaxT;
        int kbase = (fr ? bx - 384 : bx) * 2;
        int tx = t & 127, ty = t >> 7;
        for (int i = t; i < 1024; i += 256) {
            int yy = i >> 9, c = i & 511;
            int ky = kbase + yy;
            Wcol[yy][c] = cw[(ky & 255) * 4608 + c * 9 + (ky >> 8) * 3 + 1];
        }
        __syncthreads();
        float acc = 0.0f;
#pragma unroll 8
        for (int c = 0; c < 512; c++)
            acc += vmax[c * 128 + tx] * Wcol[ty][c];
        int addr = (kbase + ty) * 128 + tx;
        uint32_t hi = f2tf32(acc);
        if (fr) {
            g_U2Tfhi[addr] = hi;
        } else {
            g_U2Thi[addr] = hi;
            g_U2Tlo[addr] = f2tf32(acc - __uint_as_float(hi));
        }
    } else if (bx == 768) {               // ---- lsum2 -> fconst ----
        int j = t & 127, half = t >> 7;
        float s = 0.0f;
        int o0 = half * 128;
        for (int o = o0; o < o0 + 128; o++) s += g_tmp[o * 128 + j];
        s2[t] = s;
        __syncthreads();
        if (t < 128) g_fconst[t] = e_lb[t] + s2[t] + s2[t + 128];
    } else if (bx < 2817) {               // ---- lwf2 ----
        int blk = bx - 769;
        for (int i = t; i < 2048; i += 256)
            lr[i >> 7][i & 127] = f_lw1[(size_t)blk * 2048 + i];
        for (int i = t; i < 2048; i += 256) {
            int j = i >> 4, v = i & 15;
            l2[j][v] = (v < 14) ? f_l2w[j * 14 + v] : 0.0f;
        }
        __syncthreads();
        int r = t >> 4, v = t & 15;
        float acc = 0.0f;
#pragma unroll 8
        for (int j = 0; j < 128; j++)
            acc += lr[r][j] * l2[j][v];
        g_lwF2[(size_t)(blk * 16 + r) * 16 + v] = acc;
    } else {                              // ---- fc2a from Sf ----
        int blk = bx - 2817;              // 0..15
        int o = blk * 16 + (t >> 4), v = t & 15;
        float acc = 0.0f;
        if (v < 14)
            for (int j = 0; j < 128; j++)
                acc += g_Sf[o * 128 + j] * f_l2w[j * 14 + v];
        g_tmpf[o * 16 + v] = f_cb[o] * acc;
    }
}

// ===========================================================================
// LAYER 3: ggemm_e (256 blk) | ggemm_f (128 blk) | fc2b (1 blk)
//   grid 385 x 256, dyn smem 44032 B  (R8 exact — proven)
// ===========================================================================
#define ASTR 136
#define BSTR 72
#define AWORDS (16 * ASTR)               // 2176
#define BWORDS (16 * BSTR)               // 1152
#define AOFFALL (4 * AWORDS)             // 8704
#define SME_BYTES ((4 * AWORDS + 2 * BWORDS) * 4)   // 44032

__global__ void __launch_bounds__(256, 2) stage3(
    const float* __restrict__ e_lw,
    const float* __restrict__ f_lb, const float* __restrict__ f_l2w,
    const float* __restrict__ f_l2b)
{
    extern __shared__ uint32_t sm[];
    int bx = blockIdx.x, t = threadIdx.x;
    int lane = t & 31;
    int wid  = t >> 5;
    int gid  = lane >> 2;
    int tig  = lane & 3;
    uint32_t sbase = (uint32_t)__cvta_generic_to_shared(sm);

    if (bx < 256) {
        // ================= ggemm_e: 3xTF32, raw-B conversion =================
        int hh = bx >> 1, by = bx & 1;
        int wm = wid & 3, wn = wid >> 2;

        float acc[2][4][4];
#pragma unroll
        for (int i = 0; i < 2; i++)
#pragma unroll
            for (int j = 0; j < 4; j++)
#pragma unroll
                for (int q = 0; q < 4; q++) acc[i][j][q] = 0.0f;

        auto load_stage = [&](int s, int k0) {
#pragma unroll
            for (int pl = 0; pl < 2; pl++) {
#pragma unroll
                for (int q = 0; q < 2; q++) {
                    int c   = t * 2 + q;
                    int row = c >> 5;
                    int c4  = (c & 31) * 4;
                    uint32_t sa = sbase + (uint32_t)(((s * 2 + pl) * AWORDS + row * ASTR + c4) * 4);
                    const uint32_t* g = (pl ? g_U2Tlo : g_U2Thi) + (size_t)(k0 + row) * 128 + c4;
                    cp16(sa, g);
                }
            }
            {
                int row = t >> 4;
                int c4  = (t & 15) * 4;
                int k   = k0 + row;
                int tap = k >> 8, o = k & 255;
                int h   = hh + 1 - tap;
                int ok  = (h >= 0 && h < 128) ? 16 : 0;
                const float* g = e_lw + (ok ? ((size_t)(o * 128 + h) * 128 + by * 64 + c4) : 0);
                uint32_t sa = sbase + (uint32_t)((AOFFALL + s * BWORDS + row * BSTR + c4) * 4);
                cp16z(sa, g, ok);
            }
            cp_commit();
        };

        const int NIT = KTOT / 16;   // 48
        load_stage(0, 0);

        for (int it = 0; it < NIT; it++) {
            if (it + 1 < NIT) {
                load_stage((it + 1) & 1, (it + 1) * 16);
                asm volatile("cp.async.wait_group 1;");
            } else {
                asm volatile("cp.async.wait_group 0;");
            }
            __syncthreads();

            int s = it & 1;
            const uint32_t* A0 = sm + (s * 2 + 0) * AWORDS;
            const uint32_t* A1 = sm + (s * 2 + 1) * AWORDS;
            const float*    Br = (const float*)(sm + AOFFALL + s * BWORDS);

#pragma unroll
            for (int ks = 0; ks < 2; ks++) {
                int kr = ks * 8;
                uint32_t af[2][2][4];
#pragma unroll
                for (int mi = 0; mi < 2; mi++) {
                    int m = wm * 32 + mi * 16;
                    af[0][mi][0] = A0[(kr + tig) * ASTR + m + gid];
                    af[0][mi][1] = A0[(kr + tig) * ASTR + m + gid + 8];
                    af[0][mi][2] = A0[(kr + tig + 4) * ASTR + m + gid];
                    af[0][mi][3] = A0[(kr + tig + 4) * ASTR + m + gid + 8];
                    af[1][mi][0] = A1[(kr + tig) * ASTR + m + gid];
                    af[1][mi][1] = A1[(kr + tig) * ASTR + m + gid + 8];
                    af[1][mi][2] = A1[(kr + tig + 4) * ASTR + m + gid];
                    af[1][mi][3] = A1[(kr + tig + 4) * ASTR + m + gid + 8];
                }
#pragma unroll
                for (int nj = 0; nj < 4; nj++) {
                    int n = wn * 32 + nj * 8;
                    float v0 = Br[(kr + tig) * BSTR + n + gid];
                    float v1 = Br[(kr + tig + 4) * BSTR + n + gid];
                    uint32_t bh[2], bl[2];
                    bh[0] = f2tf32(v0); bl[0] = f2tf32(v0 - __uint_as_float(bh[0]));
                    bh[1] = f2tf32(v1); bl[1] = f2tf32(v1 - __uint_as_float(bh[1]));
#pragma unroll
                    for (int mi = 0; mi < 2; mi++) {
                        mma8(acc[mi][nj], af[0][mi], bh);
                        mma8(acc[mi][nj], af[0][mi], bl);
                        mma8(acc[mi][nj], af[1][mi], bh);
                    }
                }
            }
            __syncthreads();
        }

        float* gbase = g_G + (size_t)hh * (128 * 128);
#pragma unroll
        for (int mi = 0; mi < 2; mi++) {
            int m = wm * 32 + mi * 16 + gid;
#pragma unroll
            for (int nj = 0; nj < 4; nj++) {
                int n = by * 64 + wn * 32 + nj * 8 + 2 * tig;
                gbase[(size_t)m * 128 + n]           = acc[mi][nj][0];
                gbase[(size_t)m * 128 + n + 1]       = acc[mi][nj][1];
                gbase[(size_t)(m + 8) * 128 + n]     = acc[mi][nj][2];
                gbase[(size_t)(m + 8) * 128 + n + 1] = acc[mi][nj][3];
            }
        }
    } else if (bx < 384) {
        // ================= ggemm_f: 8 warps x 16 M-rows, single TF32 ==========
        int hh = bx - 256;
        int wm = wid;

        float acc[2][4];
#pragma unroll
        for (int j = 0; j < 2; j++)
#pragma unroll
            for (int q = 0; q < 4; q++) acc[j][q] = 0.0f;

        const int FB = 4352;

        auto load_stage = [&](int s, int k0) {
#pragma unroll
            for (int q = 0; q < 2; q++) {
                int c   = t * 2 + q;
                int row = c >> 5;
                int c4  = (c & 31) * 4;
                uint32_t sa = sbase + (uint32_t)((s * 2176 + row * 136 + c4) * 4);
                const uint32_t* g = g_U2Tfhi + (size_t)(k0 + row) * 128 + c4;
                cp16(sa, g);
            }
            if (t < 64) {
                int row = t >> 2;
                int c4  = (t & 3) * 4;
                int k   = k0 + row;
                int tap = k >> 8, o = k & 255;
                int h   = hh + 1 - tap;
                int ok  = (h >= 0 && h < 128) ? 16 : 0;
                const float* g = g_lwF2 + (ok ? ((size_t)(o * 128 + h) * 16 + c4) : 0);
                uint32_t sa = sbase + (uint32_t)((FB + s * 384 + row * 24 + c4) * 4);
                cp16z(sa, g, ok);
            }
            cp_commit();
        };

        const int NIT = KTOT / 16;
        load_stage(0, 0);

        for (int it = 0; it < NIT; it++) {
            if (it + 1 < NIT) {
                load_stage((it + 1) & 1, (it + 1) * 16);
                asm volatile("cp.async.wait_group 1;");
            } else {
                asm volatile("cp.async.wait_group 0;");
            }
            __syncthreads();
            int s = it & 1;
            const uint32_t* A  = sm + s * 2176;
            const float*    Br = (const float*)(sm + FB + s * 384);

#pragma unroll
            for (int ks = 0; ks < 2; ks++) {
                int kr = ks * 8;
                uint32_t af[4];
                int m = wm * 16;
                af[0] = A[(kr + tig) * 136 + m + gid];
                af[1] = A[(kr + tig) * 136 + m + gid + 8];
                af[2] = A[(kr + tig + 4) * 136 + m + gid];
                af[3] = A[(kr + tig + 4) * 136 + m + gid + 8];
#pragma unroll
                for (int nj = 0; nj < 2; nj++) {
                    int n = nj * 8;
                    uint32_t bf[2];
                    bf[0] = f2tf32(Br[(kr + tig) * 24 + n + gid]);
                    bf[1] = f2tf32(Br[(kr + tig + 4) * 24 + n + gid]);
                    mma8(acc[nj], af, bf);
                }
            }
            __syncthreads();
        }

        float* gbase = g_Gf + (size_t)hh * (128 * 16);
        int m = wm * 16 + gid;
#pragma unroll
        for (int nj = 0; nj < 2; nj++) {
            int n = nj * 8 + 2 * tig;
            gbase[m * 16 + n]           = acc[nj][0];
            gbase[m * 16 + n + 1]       = acc[nj][1];
            gbase[(m + 8) * 16 + n]     = acc[nj][2];
            gbase[(m + 8) * 16 + n + 1] = acc[nj][3];
        }
    } else {
        // ================= fc2b =================
        if (t < 16) {
            int v = t;
            float s = 0.0f;
            if (v < 14) {
                s = f_l2b[v];
                for (int j = 0; j < 128; j++) s += f_lb[j] * f_l2w[j * 14 + v];
            }
            for (int o = 0; o < 256; o++) s += g_tmpf[o * 16 + v];
            g_fconst2[v] = (v < 14) ? s : 0.0f;
        }
    }
}

// ===========================================================================
// LAYER 4: fused per-batch chain, cp.async smem-staged gathers (R9 fused —
//   measured 30.4 µs vs 33.8 µs for the LDG version)
//   dyn smem 65536 B
// ===========================================================================
#define FB_SMEM 65536

__global__ void __launch_bounds__(256) fused_batch(const int* __restrict__ x,
                                                   const float* __restrict__ mcb,
                                                   const float* __restrict__ mlw,
                                                   const float* __restrict__ mlb,
                                                   float* __restrict__ out)
{
    extern __shared__ float gbuf[];       // 128 rows x 128 floats (64 KB)
    __shared__ float eo[128];
    __shared__ float rr[192];
    __shared__ int   sp[128];
    __shared__ float red[128];
    __shared__ float part2[256];
    __shared__ int   tok[256];
    __shared__ float lg[16];
    int b = blockIdx.x, t = threadIdx.x;
    uint32_t sb = (uint32_t)__cvta_generic_to_shared(gbuf);

    if (t < 128) {
        int t0 = x[b * 256 + 2 * t], t1 = x[b * 256 + 2 * t + 1];
        int a = min(t0, t1), c = max(t0, t1);
        sp[t] = a * 14 + c - ((a * (a + 1)) >> 1);
    }
    __syncthreads();

#pragma unroll
    for (int it = 0; it < 16; it++) {
        int chunk = it * 256 + t;         // 0..4095, 16B each
        int h  = chunk >> 5;
        int c4 = (chunk & 31) * 4;
        cp16(sb + chunk * 16, g_G + (size_t)((h << 7) + sp[h]) * 128 + c4);
    }
    cp_commit();
    asm volatile("cp.async.wait_group 0;");
    __syncthreads();

    {
        int j = t & 127, half = t >> 7;
        float ps = 0.0f;
        int h0 = half * 64;
#pragma unroll 8
        for (int i = 0; i < 64; i++)
            ps += gbuf[(h0 + i) * 128 + j];
        part2[t] = ps;
    }
    __syncthreads();
    float fval = 0.0f;
    if (t < 128) { fval = g_fconst[t] + part2[t] + part2[t + 128]; red[t] = fval; }
    __syncthreads();
    for (int o = 64; o > 0; o >>= 1) { if (t < o) red[t] = fmaxf(red[t], red[t + o]); __syncthreads(); }
    float mx = red[0]; __syncthreads();
    float ev = 0.0f;
    if (t < 128) { ev = expf(fval - mx); red[t] = ev; }
    __syncthreads();
    for (int o = 64; o > 0; o >>= 1) { if (t < o) red[t] += red[t + o]; __syncthreads(); }
    if (t < 128) eo[t] = ev / red[0];
    __syncthreads();

    if (t < 192) {
        int g = t / 64, o = t % 64;
        float acc = mcb[o];
        const float* wrow = g_Wsum + (g * 64 + o) * 128;
#pragma unroll 8
        for (int i = 0; i < 128; i++)
            acc += eo[i] * wrow[i];
        rr[t] = fmaxf(acc, 0.0f);
    }
    __syncthreads();

    {
        float mm = mlb[t];
#pragma unroll 4
        for (int o = 0; o < 64; o++) {
            mm += rr[o]       * mlw[(size_t)(o * 128) * 256 + t];
            mm += rr[64 + o]  * g_Lmid[o * 256 + t];
            mm += rr[128 + o] * mlw[(size_t)(o * 128 + 127) * 256 + t];
        }
        tok[t] = (int)(fmodf(floorf(fabsf(mm) * 100.0f), 14.0f));
    }
    __syncthreads();

    if (t < 128) {
        int t0 = tok[2 * t], t1 = tok[2 * t + 1];
        int a = min(t0, t1), c = max(t0, t1);
        sp[t] = a * 14 + c - ((a * (a + 1)) >> 1);
    }
    __syncthreads();

#pragma unroll
    for (int it = 0; it < 2; it++) {
        int chunk = it * 256 + t;         // 0..511
        int h  = chunk >> 2;
        int c4 = (chunk & 3) * 4;
        cp16(sb + chunk * 16, g_Gf + (size_t)((h << 7) + sp[h]) * 16 + c4);
    }
    cp_commit();
    asm volatile("cp.async.wait_group 0;");
    __syncthreads();

    if (t < 128) {
        int v = t & 15, hg = t >> 4;
        float ps = 0.0f;
#pragma unroll 4
        for (int i = 0; i < 16; i++)
            ps += gbuf[(hg * 16 + i) * 16 + v];
        part2[t] = ps;
    }
    __syncthreads();
    if (t < 16) {
        float s = g_fconst2[t];
        for (int g = 0; g < 8; g++) s += part2[g * 16 + t];
        lg[t] = s;
    }
    __syncthreads();
    if (t == 0) {
        float mx2 = lg[0];
        for (int q = 1; q < 14; q++) mx2 = fmaxf(mx2, lg[q]);
        float sum = 0.0f;
        for (int q = 0; q < 14; q++) { float e2 = expf(lg[q] - mx2); lg[q] = e2; sum += e2; }
        float inv = 1.0f / sum;
        for (int q = 0; q < 14; q++) out[b * 14 + q] = lg[q] * inv;
    }
}

// ---------------------------------------------------------------------------
// Launch: 4 layered launches
// ---------------------------------------------------------------------------
extern "C" void kernel_launch(void* const* d_in, const int* in_sizes, int n_in,
                              void* d_out, int out_size)
{
    const int*   x     = (const int*)  d_in[0];
    const float* e_emb = (const float*)d_in[1];
    const float* e_cw  = (const float*)d_in[2];
    const float* e_cb  = (const float*)d_in[3];
    const float* e_lw  = (const float*)d_in[4];
    const float* e_lb  = (const float*)d_in[5];
    // d_in[6] = rand_proj (dead: fog_of_war is provably identity)
    const float* m_cw  = (const float*)d_in[7];
    const float* m_cb  = (const float*)d_in[8];
    const float* m_lw  = (const float*)d_in[9];
    const float* m_lb  = (const float*)d_in[10];
    const float* f_emb = (const float*)d_in[11];
    const float* f_cw  = (const float*)d_in[12];
    const float* f_cb  = (const float*)d_in[13];
    const float* f_lw  = (const float*)d_in[14];
    const float* f_lb  = (const float*)d_in[15];
    const float* f_l2w = (const float*)d_in[16];
    const float* f_l2b = (const float*)d_in[17];
    float* out = (float*)d_out;

    cudaFuncSetAttribute(stage3, cudaFuncAttributeMaxDynamicSharedMemorySize, SME_BYTES);
    cudaFuncSetAttribute(fused_batch, cudaFuncAttributeMaxDynamicSharedMemorySize, FB_SMEM);

    stage1      <<<1184, 256>>>(e_emb, f_emb, e_lw, e_cb, f_lw, m_lw, m_cw);
    stage2      <<<2833, 256>>>(e_cw, f_cw, e_lb, f_lw, f_l2w, f_cb);
    stage3      <<<385, 256, SME_BYTES>>>(e_lw, f_lb, f_l2w, f_l2b);
    fused_batch <<<BB, 256, FB_SMEM>>>(x, m_cb, m_lw, m_lb, out);
}

// round 13
// speedup vs baseline: 1.1213x; 1.0391x over previous
#include <cuda_runtime.h>
#include <math.h>
#include <stdint.h>

#define BB    256
#define KTOT  768        // 3 taps * 256 conv-out channels

// ---------------------------------------------------------------------------
// Static device scratch
// ---------------------------------------------------------------------------
__device__ __align__(128) float    g_VmaxT [512 * 128];     // enemy pairwise-max emb [c][p]
__device__ __align__(128) float    g_VmaxTf[512 * 128];     // friend
__device__ __align__(128) uint32_t g_U2Thi [KTOT * 128];    // enemy U tf32 hi
__device__ __align__(128) uint32_t g_U2Tlo [KTOT * 128];    // enemy U tf32 lo
__device__ __align__(128) uint32_t g_U2Tfhi[KTOT * 128];    // friend U tf32 hi
__device__ __align__(128) float    g_G [128 * 128 * 128];   // enemy table G[h][p][j]
__device__ __align__(128) float    g_Gf[128 * 128 * 16];    // friend table G[h][p][v]
__device__ __align__(128) float    g_lwF2[32768 * 16];      // friend lin1 @ lin2
__device__ __align__(128) float    g_tmp[256 * 128];        // enemy cb[o]*colsum
__device__ __align__(128) float    g_Sf[256 * 128];         // friend lw1 h-colsums
__device__ __align__(128) float    g_fconst[128];
__device__ __align__(128) float    g_tmpf[256 * 16];
__device__ __align__(128) float    g_fconst2[16];
__device__ __align__(128) float    g_Lmid[64 * 256];
__device__ __align__(128) float    g_Wsum[3 * 64 * 128];    // manip conv weight sums
__device__ __align__(128) float    g_epart[BB * 256];       // gather_e partials [b][half*128+j]

// ---------------------------------------------------------------------------
// Helpers
// ---------------------------------------------------------------------------
__device__ __forceinline__ uint32_t f2tf32(float x) {
    uint32_t r;
    asm("cvt.rna.tf32.f32 %0, %1;" : "=r"(r) : "f"(x));
    return r;
}
__device__ __forceinline__ void mma8(float* c, const uint32_t* a, const uint32_t* b) {
    asm volatile(
        "mma.sync.aligned.m16n8k8.row.col.f32.tf32.tf32.f32 "
        "{%0,%1,%2,%3}, {%4,%5,%6,%7}, {%8,%9}, {%0,%1,%2,%3};"
        : "+f"(c[0]), "+f"(c[1]), "+f"(c[2]), "+f"(c[3])
        : "r"(a[0]), "r"(a[1]), "r"(a[2]), "r"(a[3]), "r"(b[0]), "r"(b[1]));
}
__device__ __forceinline__ void cp16(uint32_t saddr, const void* g) {
    asm volatile("cp.async.cg.shared.global [%0], [%1], 16;" :: "r"(saddr), "l"(g));
}
__device__ __forceinline__ void cp16z(uint32_t saddr, const void* g, int srcsz) {
    asm volatile("cp.async.cg.shared.global [%0], [%1], 16, %2;"
                 :: "r"(saddr), "l"(g), "r"(srcsz));
}
__device__ __forceinline__ void cp_commit() {
    asm volatile("cp.async.commit_group;");
}

// ===========================================================================
// LAYER 1: vmax (e+f) | lw column-sums (e+f) | prep (Lmid + Wsum)
//   grid 1184 x 256   (R8 exact — proven)
// ===========================================================================
__global__ void __launch_bounds__(256) stage1(
    const float* __restrict__ e_emb, const float* __restrict__ f_emb,
    const float* __restrict__ e_lw,  const float* __restrict__ e_cb,
    const float* __restrict__ f_lw,
    const float* __restrict__ mlw,   const float* __restrict__ mcw)
{
    __shared__ float sred[256];
    int bx = blockIdx.x, t = threadIdx.x;

    if (bx < 512) {                       // ---- vmax both ----
        bool fr = bx >= 256;
        int idx = (fr ? bx - 256 : bx) * 256 + t;
        int c = idx >> 7, p = idx & 127;
        const float* emb = fr ? f_emb : e_emb;
        float v = 0.0f;
        if (p < 105) {
            int a = 0, rem = p;
            while (rem >= 14 - a) { rem -= 14 - a; a++; }
            int b = a + rem;
            v = fmaxf(emb[a * 512 + c], emb[b * 512 + c]);
        }
        (fr ? g_VmaxTf : g_VmaxT)[idx] = v;
    } else if (bx < 1024) {               // ---- lw column sums (e / f) ----
        bool fr = bx >= 768;
        int o = fr ? bx - 768 : bx - 512;
        const float* lw = fr ? f_lw : e_lw;
        int j = t & 127, hoff = t >> 7;
        float sum = 0.0f;
        for (int h2 = 0; h2 < 64; h2++) {
            int h = h2 * 2 + hoff;
            sum += lw[(size_t)(o * 128 + h) * 128 + j];
        }
        sred[t] = sum;
        __syncthreads();
        if (t < 128) {
            float s = sred[t] + sred[t + 128];
            if (fr) g_Sf[o * 128 + t] = s;
            else    g_tmp[o * 128 + t] = e_cb[o] * s;
        }
    } else {                              // ---- prep: Lmid + Wsum ----
        int idx = (bx - 1024) * 256 + t;  // < 40960
        if (idx < 16384) {
            int o = idx >> 8, j = idx & 255;
            float s = 0.0f;
            for (int h = 1; h <= 126; h++)
                s += mlw[(size_t)(o * 128 + h) * 256 + j];
            g_Lmid[idx] = s;
        } else {
            int k = idx - 16384;          // < 24576
            int row = k >> 7, i = k & 127;
            int g = row >> 6, o = row & 63;
            const float* wp = mcw + o * 1152 + i * 9;
            float w0 = wp[1], w1 = wp[4], w2 = wp[7];
            float ws = (g == 0) ? (w1 + w2) : ((g == 1) ? (w0 + w1 + w2) : (w0 + w1));
            g_Wsum[(g * 64 + o) * 128 + i] = ws;
        }
    }
}

// ===========================================================================
// LAYER 2: u_both (4 k/block, 384 blk) | lsum2 | lwf2 (2048) | fc2a (16)
//   grid 2449 x 256.  Wcol[4][512]=8KB keeps static smem at 25KB -> 8 blk/SM.
// ===========================================================================
__global__ void __launch_bounds__(256) stage2(
    const float* __restrict__ e_cw, const float* __restrict__ f_cw,
    const float* __restrict__ e_lb,
    const float* __restrict__ f_lw1, const float* __restrict__ f_l2w,
    const float* __restrict__ f_cb)
{
    __shared__ float Wcol[4][512];
    __shared__ float lr[16][128];
    __shared__ float l2[128][16];
    __shared__ float s2[256];
    int bx = blockIdx.x, t = threadIdx.x;

    if (bx < 384) {                       // ---- u for both branches, 4 k each ----
        bool fr = bx >= 192;
        const float* cw   = fr ? f_cw : e_cw;
        const float* vmax = fr ? g_VmaxTf : g_VmaxT;
        int kbase = (fr ? bx - 192 : bx) * 4;
        int tx = t & 127, tg = t >> 7;    // tg in {0,1}: k rows tg*2, tg*2+1
        for (int i = t; i < 2048; i += 256) {
            int yy = i >> 9, c = i & 511;
            int ky = kbase + yy;
            Wcol[yy][c] = cw[(ky & 255) * 4608 + c * 9 + (ky >> 8) * 3 + 1];
        }
        __syncthreads();
        float acc[2] = {0.0f, 0.0f};
#pragma unroll 8
        for (int c = 0; c < 512; c++) {
            float v = vmax[c * 128 + tx];
            acc[0] += v * Wcol[tg * 2][c];
            acc[1] += v * Wcol[tg * 2 + 1][c];
        }
#pragma unroll
        for (int i = 0; i < 2; i++) {
            int addr = (kbase + tg * 2 + i) * 128 + tx;
            uint32_t hi = f2tf32(acc[i]);
            if (fr) {
                g_U2Tfhi[addr] = hi;
            } else {
                g_U2Thi[addr] = hi;
                g_U2Tlo[addr] = f2tf32(acc[i] - __uint_as_float(hi));
            }
        }
    } else if (bx == 384) {               // ---- lsum2 -> fconst ----
        int j = t & 127, half = t >> 7;
        float s = 0.0f;
        int o0 = half * 128;
        for (int o = o0; o < o0 + 128; o++) s += g_tmp[o * 128 + j];
        s2[t] = s;
        __syncthreads();
        if (t < 128) g_fconst[t] = e_lb[t] + s2[t] + s2[t + 128];
    } else if (bx < 2433) {               // ---- lwf2 ----
        int blk = bx - 385;               // 0..2047
        for (int i = t; i < 2048; i += 256)
            lr[i >> 7][i & 127] = f_lw1[(size_t)blk * 2048 + i];
        for (int i = t; i < 2048; i += 256) {
            int j = i >> 4, v = i & 15;
            l2[j][v] = (v < 14) ? f_l2w[j * 14 + v] : 0.0f;
        }
        __syncthreads();
        int r = t >> 4, v = t & 15;
        float acc = 0.0f;
#pragma unroll 8
        for (int j = 0; j < 128; j++)
            acc += lr[r][j] * l2[j][v];
        g_lwF2[(size_t)(blk * 16 + r) * 16 + v] = acc;
    } else {                              // ---- fc2a from Sf ----
        int blk = bx - 2433;              // 0..15
        int o = blk * 16 + (t >> 4), v = t & 15;
        float acc = 0.0f;
        if (v < 14)
            for (int j = 0; j < 128; j++)
                acc += g_Sf[o * 128 + j] * f_l2w[j * 14 + v];
        g_tmpf[o * 16 + v] = f_cb[o] * acc;
    }
}

// ===========================================================================
// LAYER 3: ggemm_e (256 blk) | ggemm_f (128 blk) | fc2b (1 blk)
//   grid 385 x 256, dyn smem 44032 B  (R8 exact — proven)
// ===========================================================================
#define ASTR 136
#define BSTR 72
#define AWORDS (16 * ASTR)               // 2176
#define BWORDS (16 * BSTR)               // 1152
#define AOFFALL (4 * AWORDS)             // 8704
#define SME_BYTES ((4 * AWORDS + 2 * BWORDS) * 4)   // 44032

__global__ void __launch_bounds__(256, 2) stage3(
    const float* __restrict__ e_lw,
    const float* __restrict__ f_lb, const float* __restrict__ f_l2w,
    const float* __restrict__ f_l2b)
{
    extern __shared__ uint32_t sm[];
    int bx = blockIdx.x, t = threadIdx.x;
    int lane = t & 31;
    int wid  = t >> 5;
    int gid  = lane >> 2;
    int tig  = lane & 3;
    uint32_t sbase = (uint32_t)__cvta_generic_to_shared(sm);

    if (bx < 256) {
        // ================= ggemm_e: 3xTF32, raw-B conversion =================
        int hh = bx >> 1, by = bx & 1;
        int wm = wid & 3, wn = wid >> 2;

        float acc[2][4][4];
#pragma unroll
        for (int i = 0; i < 2; i++)
#pragma unroll
            for (int j = 0; j < 4; j++)
#pragma unroll
                for (int q = 0; q < 4; q++) acc[i][j][q] = 0.0f;

        auto load_stage = [&](int s, int k0) {
#pragma unroll
            for (int pl = 0; pl < 2; pl++) {
#pragma unroll
                for (int q = 0; q < 2; q++) {
                    int c   = t * 2 + q;
                    int row = c >> 5;
                    int c4  = (c & 31) * 4;
                    uint32_t sa = sbase + (uint32_t)(((s * 2 + pl) * AWORDS + row * ASTR + c4) * 4);
                    const uint32_t* g = (pl ? g_U2Tlo : g_U2Thi) + (size_t)(k0 + row) * 128 + c4;
                    cp16(sa, g);
                }
            }
            {
                int row = t >> 4;
                int c4  = (t & 15) * 4;
                int k   = k0 + row;
                int tap = k >> 8, o = k & 255;
                int h   = hh + 1 - tap;
                int ok  = (h >= 0 && h < 128) ? 16 : 0;
                const float* g = e_lw + (ok ? ((size_t)(o * 128 + h) * 128 + by * 64 + c4) : 0);
                uint32_t sa = sbase + (uint32_t)((AOFFALL + s * BWORDS + row * BSTR + c4) * 4);
                cp16z(sa, g, ok);
            }
            cp_commit();
        };

        const int NIT = KTOT / 16;   // 48
        load_stage(0, 0);

        for (int it = 0; it < NIT; it++) {
            if (it + 1 < NIT) {
                load_stage((it + 1) & 1, (it + 1) * 16);
                asm volatile("cp.async.wait_group 1;");
            } else {
                asm volatile("cp.async.wait_group 0;");
            }
            __syncthreads();

            int s = it & 1;
            const uint32_t* A0 = sm + (s * 2 + 0) * AWORDS;
            const uint32_t* A1 = sm + (s * 2 + 1) * AWORDS;
            const float*    Br = (const float*)(sm + AOFFALL + s * BWORDS);

#pragma unroll
            for (int ks = 0; ks < 2; ks++) {
                int kr = ks * 8;
                uint32_t af[2][2][4];
#pragma unroll
                for (int mi = 0; mi < 2; mi++) {
                    int m = wm * 32 + mi * 16;
                    af[0][mi][0] = A0[(kr + tig) * ASTR + m + gid];
                    af[0][mi][1] = A0[(kr + tig) * ASTR + m + gid + 8];
                    af[0][mi][2] = A0[(kr + tig + 4) * ASTR + m + gid];
                    af[0][mi][3] = A0[(kr + tig + 4) * ASTR + m + gid + 8];
                    af[1][mi][0] = A1[(kr + tig) * ASTR + m + gid];
                    af[1][mi][1] = A1[(kr + tig) * ASTR + m + gid + 8];
                    af[1][mi][2] = A1[(kr + tig + 4) * ASTR + m + gid];
                    af[1][mi][3] = A1[(kr + tig + 4) * ASTR + m + gid + 8];
                }
#pragma unroll
                for (int nj = 0; nj < 4; nj++) {
                    int n = wn * 32 + nj * 8;
                    float v0 = Br[(kr + tig) * BSTR + n + gid];
                    float v1 = Br[(kr + tig + 4) * BSTR + n + gid];
                    uint32_t bh[2], bl[2];
                    bh[0] = f2tf32(v0); bl[0] = f2tf32(v0 - __uint_as_float(bh[0]));
                    bh[1] = f2tf32(v1); bl[1] = f2tf32(v1 - __uint_as_float(bh[1]));
#pragma unroll
                    for (int mi = 0; mi < 2; mi++) {
                        mma8(acc[mi][nj], af[0][mi], bh);
                        mma8(acc[mi][nj], af[0][mi], bl);
                        mma8(acc[mi][nj], af[1][mi], bh);
                    }
                }
            }
            __syncthreads();
        }

        float* gbase = g_G + (size_t)hh * (128 * 128);
#pragma unroll
        for (int mi = 0; mi < 2; mi++) {
            int m = wm * 32 + mi * 16 + gid;
#pragma unroll
            for (int nj = 0; nj < 4; nj++) {
                int n = by * 64 + wn * 32 + nj * 8 + 2 * tig;
                gbase[(size_t)m * 128 + n]           = acc[mi][nj][0];
                gbase[(size_t)m * 128 + n + 1]       = acc[mi][nj][1];
                gbase[(size_t)(m + 8) * 128 + n]     = acc[mi][nj][2];
                gbase[(size_t)(m + 8) * 128 + n + 1] = acc[mi][nj][3];
            }
        }
    } else if (bx < 384) {
        // ================= ggemm_f: 8 warps x 16 M-rows, single TF32 ==========
        int hh = bx - 256;
        int wm = wid;

        float acc[2][4];
#pragma unroll
        for (int j = 0; j < 2; j++)
#pragma unroll
            for (int q = 0; q < 4; q++) acc[j][q] = 0.0f;

        const int FB = 4352;

        auto load_stage = [&](int s, int k0) {
#pragma unroll
            for (int q = 0; q < 2; q++) {
                int c   = t * 2 + q;
                int row = c >> 5;
                int c4  = (c & 31) * 4;
                uint32_t sa = sbase + (uint32_t)((s * 2176 + row * 136 + c4) * 4);
                const uint32_t* g = g_U2Tfhi + (size_t)(k0 + row) * 128 + c4;
                cp16(sa, g);
            }
            if (t < 64) {
                int row = t >> 2;
                int c4  = (t & 3) * 4;
                int k   = k0 + row;
                int tap = k >> 8, o = k & 255;
                int h   = hh + 1 - tap;
                int ok  = (h >= 0 && h < 128) ? 16 : 0;
                const float* g = g_lwF2 + (ok ? ((size_t)(o * 128 + h) * 16 + c4) : 0);
                uint32_t sa = sbase + (uint32_t)((FB + s * 384 + row * 24 + c4) * 4);
                cp16z(sa, g, ok);
            }
            cp_commit();
        };

        const int NIT = KTOT / 16;
        load_stage(0, 0);

        for (int it = 0; it < NIT; it++) {
            if (it + 1 < NIT) {
                load_stage((it + 1) & 1, (it + 1) * 16);
                asm volatile("cp.async.wait_group 1;");
            } else {
                asm volatile("cp.async.wait_group 0;");
            }
            __syncthreads();
            int s = it & 1;
            const uint32_t* A  = sm + s * 2176;
            const float*    Br = (const float*)(sm + FB + s * 384);

#pragma unroll
            for (int ks = 0; ks < 2; ks++) {
                int kr = ks * 8;
                uint32_t af[4];
                int m = wm * 16;
                af[0] = A[(kr + tig) * 136 + m + gid];
                af[1] = A[(kr + tig) * 136 + m + gid + 8];
                af[2] = A[(kr + tig + 4) * 136 + m + gid];
                af[3] = A[(kr + tig + 4) * 136 + m + gid + 8];
#pragma unroll
                for (int nj = 0; nj < 2; nj++) {
                    int n = nj * 8;
                    uint32_t bf[2];
                    bf[0] = f2tf32(Br[(kr + tig) * 24 + n + gid]);
                    bf[1] = f2tf32(Br[(kr + tig + 4) * 24 + n + gid]);
                    mma8(acc[nj], af, bf);
                }
            }
            __syncthreads();
        }

        float* gbase = g_Gf + (size_t)hh * (128 * 16);
        int m = wm * 16 + gid;
#pragma unroll
        for (int nj = 0; nj < 2; nj++) {
            int n = nj * 8 + 2 * tig;
            gbase[m * 16 + n]           = acc[nj][0];
            gbase[m * 16 + n + 1]       = acc[nj][1];
            gbase[(m + 8) * 16 + n]     = acc[nj][2];
            gbase[(m + 8) * 16 + n + 1] = acc[nj][3];
        }
    } else {
        // ================= fc2b =================
        if (t < 16) {
            int v = t;
            float s = 0.0f;
            if (v < 14) {
                s = f_l2b[v];
                for (int j = 0; j < 128; j++) s += f_lb[j] * f_l2w[j * 14 + v];
            }
            for (int o = 0; o < 256; o++) s += g_tmpf[o * 16 + v];
            g_fconst2[v] = (v < 14) ? s : 0.0f;
        }
    }
}

// ===========================================================================
// LAYER 4a: gather_e partials. grid (512) = (b, half), 128 threads.
//   Thread j sums h = half*64 + i, i = 0..63 sequentially (exact R8 order).
// ===========================================================================
__global__ void __launch_bounds__(128) gpart_kernel(const int* __restrict__ x)
{
    __shared__ int sp[64];
    int bx = blockIdx.x;
    int b = bx >> 1, half = bx & 1;
    int t = threadIdx.x;
    if (t < 64) {
        int h = half * 64 + t;
        int t0 = x[b * 256 + 2 * h], t1 = x[b * 256 + 2 * h + 1];
        int a = min(t0, t1), c = max(t0, t1);
        sp[t] = a * 14 + c - ((a * (a + 1)) >> 1);
    }
    __syncthreads();
    int h0 = half * 64;
    float ps = 0.0f;
#pragma unroll 8
    for (int i = 0; i < 64; i++)
        ps += g_G[(size_t)(((h0 + i) << 7) + sp[i]) * 128 + t];
    g_epart[b * 256 + half * 128 + t] = ps;
}

// ===========================================================================
// LAYER 4b: per-batch chain (softmax -> manip -> tokens -> gather_f -> out)
//   grid 256 x 256, small smem, high occupancy.
// ===========================================================================
__global__ void __launch_bounds__(256) fused2(const float* __restrict__ mcb,
                                              const float* __restrict__ mlw,
                                              const float* __restrict__ mlb,
                                              float* __restrict__ out)
{
    __shared__ float eo[128];
    __shared__ float rr[192];
    __shared__ int   sp[128];
    __shared__ float red[128];
    __shared__ float part2[128];
    __shared__ int   tok[256];
    __shared__ float lg[16];
    int b = blockIdx.x, t = threadIdx.x;

    // ---- combine partials (exact order: fconst + half0 + half1) + softmax ----
    float fval = 0.0f;
    if (t < 128) {
        fval = g_fconst[t] + g_epart[b * 256 + t] + g_epart[b * 256 + 128 + t];
        red[t] = fval;
    }
    __syncthreads();
    for (int o = 64; o > 0; o >>= 1) { if (t < o) red[t] = fmaxf(red[t], red[t + o]); __syncthreads(); }
    float mx = red[0]; __syncthreads();
    float ev = 0.0f;
    if (t < 128) { ev = expf(fval - mx); red[t] = ev; }
    __syncthreads();
    for (int o = 64; o > 0; o >>= 1) { if (t < o) red[t] += red[t + o]; __syncthreads(); }
    if (t < 128) eo[t] = ev / red[0];
    __syncthreads();

    // ---- manip conv ----
    if (t < 192) {
        int g = t / 64, o = t % 64;
        float acc = mcb[o];
        const float* wrow = g_Wsum + (g * 64 + o) * 128;
#pragma unroll 8
        for (int i = 0; i < 128; i++)
            acc += eo[i] * wrow[i];
        rr[t] = fmaxf(acc, 0.0f);
    }
    __syncthreads();

    // ---- manip linear + token quantization ----
    {
        float mm = mlb[t];
#pragma unroll 4
        for (int o = 0; o < 64; o++) {
            mm += rr[o]       * mlw[(size_t)(o * 128) * 256 + t];
            mm += rr[64 + o]  * g_Lmid[o * 256 + t];
            mm += rr[128 + o] * mlw[(size_t)(o * 128 + 127) * 256 + t];
        }
        tok[t] = (int)(fmodf(floorf(fabsf(mm) * 100.0f), 14.0f));
    }
    __syncthreads();

    // ---- friend pair indices ----
    if (t < 128) {
        int t0 = tok[2 * t], t1 = tok[2 * t + 1];
        int a = min(t0, t1), c = max(t0, t1);
        sp[t] = a * 14 + c - ((a * (a + 1)) >> 1);
    }
    __syncthreads();

    // ---- gather_f (direct; 16 loads/thread, L2-resident Gf) ----
    if (t < 128) {
        int v = t & 15, hg = t >> 4;
        float ps = 0.0f;
#pragma unroll 8
        for (int i = 0; i < 16; i++) {
            int h = hg * 16 + i;
            ps += g_Gf[(size_t)((h << 7) + sp[h]) * 16 + v];
        }
        part2[t] = ps;
    }
    __syncthreads();
    if (t < 16) {
        float s = g_fconst2[t];
        for (int g = 0; g < 8; g++) s += part2[g * 16 + t];
        lg[t] = s;
    }
    __syncthreads();
    if (t == 0) {
        float mx2 = lg[0];
        for (int q = 1; q < 14; q++) mx2 = fmaxf(mx2, lg[q]);
        float sum = 0.0f;
        for (int q = 0; q < 14; q++) { float e2 = expf(lg[q] - mx2); lg[q] = e2; sum += e2; }
        float inv = 1.0f / sum;
        for (int q = 0; q < 14; q++) out[b * 14 + q] = lg[q] * inv;
    }
}

// ---------------------------------------------------------------------------
// Launch: 5 layered launches
// ---------------------------------------------------------------------------
extern "C" void kernel_launch(void* const* d_in, const int* in_sizes, int n_in,
                              void* d_out, int out_size)
{
    const int*   x     = (const int*)  d_in[0];
    const float* e_emb = (const float*)d_in[1];
    const float* e_cw  = (const float*)d_in[2];
    const float* e_cb  = (const float*)d_in[3];
    const float* e_lw  = (const float*)d_in[4];
    const float* e_lb  = (const float*)d_in[5];
    // d_in[6] = rand_proj (dead: fog_of_war is provably identity)
    const float* m_cw  = (const float*)d_in[7];
    const float* m_cb  = (const float*)d_in[8];
    const float* m_lw  = (const float*)d_in[9];
    const float* m_lb  = (const float*)d_in[10];
    const float* f_emb = (const float*)d_in[11];
    const float* f_cw  = (const float*)d_in[12];
    const float* f_cb  = (const float*)d_in[13];
    const float* f_lw  = (const float*)d_in[14];
    const float* f_lb  = (const float*)d_in[15];
    const float* f_l2w = (const float*)d_in[16];
    const float* f_l2b = (const float*)d_in[17];
    float* out = (float*)d_out;

    cudaFuncSetAttribute(stage3, cudaFuncAttributeMaxDynamicSharedMemorySize, SME_BYTES);

    stage1       <<<1184, 256>>>(e_emb, f_emb, e_lw, e_cb, f_lw, m_lw, m_cw);
    stage2       <<<2449, 256>>>(e_cw, f_cw, e_lb, f_lw, f_l2w, f_cb);
    stage3       <<<385, 256, SME_BYTES>>>(e_lw, f_lb, f_l2w, f_l2b);
    gpart_kernel <<<512, 128>>>(x);
    fused2       <<<BB, 256>>>(m_cb, m_lw, m_lb, out);
}